// round 1
// baseline (speedup 1.0000x reference)
#include <cuda_runtime.h>
#include <math.h>

#define NB 256
#define NR 36
#define NL 40
#define ND 1024
#define EPSF 1e-8f
#define LAMS 9.0f
#define LAML 6.0f

// ---- scratch (device globals; no allocation allowed) ----
__device__ float g_P[NB * NB * NR];   // P[i][b*36+r] = img_emb[b,r] . pool_txt[i]
__device__ float g_Q[NB * NB * NL];   // Q[b][i*40+l] = cap_emb[i,l] . pool_img[b]
__device__ float g_G[NB * NR * NR];   // per-image region Gram
__device__ float g_H[NB * NL * NL];   // per-caption word Gram
__device__ float g_base[NB * NB];     // pool_img @ pool_txt^T
__device__ float g_w1i[NB];
__device__ float g_w1t[NB];

__device__ __forceinline__ float4 ldg4(const float* p) {
    return *reinterpret_cast<const float4*>(p);
}

// ---- pool norms ----
__global__ void norm_kernel(const float* __restrict__ pi, const float* __restrict__ pt) {
    int w = blockIdx.x * 8 + (threadIdx.x >> 5);   // 64 blocks * 8 warps = 512 rows
    int lane = threadIdx.x & 31;
    const float* src = (w < NB) ? (pi + (size_t)w * ND) : (pt + (size_t)(w - NB) * ND);
    float s = 0.f;
    for (int j = lane; j < ND; j += 32) { float v = src[j]; s = fmaf(v, v, s); }
#pragma unroll
    for (int o = 16; o; o >>= 1) s += __shfl_down_sync(0xffffffffu, s, o);
    if (lane == 0) {
        float r = sqrtf(s);
        if (w < NB) g_w1i[w] = r; else g_w1t[w - NB] = r;
    }
}

// ---- C[m][n] = sum_k A[m][k]*B[n][k]; M,N multiples of 64, K mult of 16 ----
__global__ void sgemm_tn(const float* __restrict__ A, const float* __restrict__ Bm,
                         int M, int N, int K, int dst) {
    float* C = (dst == 0) ? g_P : (dst == 1) ? g_Q : g_base;
    __shared__ float As[16 * 64];
    __shared__ float Bs[16 * 64];
    int tid = threadIdx.x;
    int tx = tid & 15, ty = tid >> 4;
    int m0 = blockIdx.y * 64, n0 = blockIdx.x * 64;
    int row = tid >> 2, q = tid & 3;
    float acc[4][4] = {};
    for (int k0 = 0; k0 < K; k0 += 16) {
        float4 a = ldg4(A + (size_t)(m0 + row) * K + k0 + q * 4);
        float4 bb = ldg4(Bm + (size_t)(n0 + row) * K + k0 + q * 4);
        As[(q * 4 + 0) * 64 + row] = a.x;  As[(q * 4 + 1) * 64 + row] = a.y;
        As[(q * 4 + 2) * 64 + row] = a.z;  As[(q * 4 + 3) * 64 + row] = a.w;
        Bs[(q * 4 + 0) * 64 + row] = bb.x; Bs[(q * 4 + 1) * 64 + row] = bb.y;
        Bs[(q * 4 + 2) * 64 + row] = bb.z; Bs[(q * 4 + 3) * 64 + row] = bb.w;
        __syncthreads();
#pragma unroll
        for (int k = 0; k < 16; k++) {
            float4 av = *(const float4*)(As + k * 64 + ty * 4);
            float4 bv = *(const float4*)(Bs + k * 64 + tx * 4);
            float aa[4] = {av.x, av.y, av.z, av.w};
            float bw[4] = {bv.x, bv.y, bv.z, bv.w};
#pragma unroll
            for (int ii = 0; ii < 4; ii++)
#pragma unroll
                for (int jj = 0; jj < 4; jj++)
                    acc[ii][jj] = fmaf(aa[ii], bw[jj], acc[ii][jj]);
        }
        __syncthreads();
    }
#pragma unroll
    for (int ii = 0; ii < 4; ii++)
#pragma unroll
        for (int jj = 0; jj < 4; jj++)
            C[(size_t)(m0 + ty * 4 + ii) * N + n0 + tx * 4 + jj] = acc[ii][jj];
}

// ---- per-row Gram: out[b] = E E^T, E = emb[b] (ROWS x 1024) ----
__global__ void gram_kernel(const float* __restrict__ emb, int ROWS, int which) {
    extern __shared__ float Es[];
    float* out = which ? g_H : g_G;
    int b = blockIdx.x, tid = threadIdx.x;
    int n = ROWS * ND;
    for (int idx = tid; idx < n; idx += 256) Es[idx] = emb[(size_t)b * n + idx];
    __syncthreads();
    int wid = tid >> 5, lane = tid & 31;
    int np = ROWS * ROWS;
    for (int p = wid; p < np; p += 8) {
        int r = p / ROWS, r2 = p - r * ROWS;
        const float* e1 = Es + r * ND;
        const float* e2 = Es + r2 * ND;
        float s = 0.f;
        for (int j = lane; j < ND; j += 32) s = fmaf(e1[j], e2[j], s);
#pragma unroll
        for (int o = 16; o; o >>= 1) s += __shfl_down_sync(0xffffffffu, s, o);
        if (lane == 0) out[(size_t)b * np + p] = s;
    }
}

// ---- main fused pair kernel: one block per (caption i, image b) ----
__global__ void __launch_bounds__(96) pair_kernel(const float* __restrict__ img_emb,
                                                  const float* __restrict__ cap_emb,
                                                  float* __restrict__ out) {
    __shared__ float sh[7680];
    const int i = blockIdx.x;       // caption
    const int b = blockIdx.y;       // image
    const int tid = threadIdx.x;
    const bool act = tid < 90;
    const int ty = act ? tid / 10 : 0;   // r-group (0..8) -> rows 4*ty..4*ty+3
    const int tx = act ? tid % 10 : 0;   // l-group (0..9) -> cols 4*tx..4*tx+3
    const float* Ib = img_emb + (size_t)b * NR * ND;
    const float* Ci = cap_emb + (size_t)i * NL * ND;
    float acc[4][4] = {};

    // ---- phase 1: S = Ib . Ci^T, K streamed in 32-chunks, double buffered ----
    // smem: imgS buf c at sh + c*1152 ([k][r], 32x36), capS buf c at sh+2304 + c*1280 ([k][l], 32x40)
    for (int v = tid; v < 608; v += 96) {            // prologue chunk 0
        if (v < 288) {
            int r = v >> 3, q = v & 7;
            float4 t = ldg4(Ib + r * ND + q * 4);
            int k = q * 4;
            sh[(k + 0) * 36 + r] = t.x; sh[(k + 1) * 36 + r] = t.y;
            sh[(k + 2) * 36 + r] = t.z; sh[(k + 3) * 36 + r] = t.w;
        } else {
            int v2 = v - 288; int l = v2 >> 3, q = v2 & 7;
            float4 t = ldg4(Ci + l * ND + q * 4);
            int k = q * 4; float* cs = sh + 2304;
            cs[(k + 0) * 40 + l] = t.x; cs[(k + 1) * 40 + l] = t.y;
            cs[(k + 2) * 40 + l] = t.z; cs[(k + 3) * 40 + l] = t.w;
        }
    }
    __syncthreads();

    for (int c = 0; c < 32; c++) {
        int cur = c & 1;
        float4 tmp[7];
        if (c < 31) {
            int k0 = (c + 1) * 32;
#pragma unroll
            for (int j = 0; j < 7; j++) {
                int v = tid + j * 96;
                if (v < 608) {
                    if (v < 288) { int r = v >> 3, q = v & 7; tmp[j] = ldg4(Ib + r * ND + k0 + q * 4); }
                    else { int v2 = v - 288; int l = v2 >> 3, q = v2 & 7; tmp[j] = ldg4(Ci + l * ND + k0 + q * 4); }
                }
            }
        }
        const float* ib = sh + cur * 1152;
        const float* cb = sh + 2304 + cur * 1280;
#pragma unroll
        for (int k = 0; k < 32; k++) {
            float4 av = *(const float4*)(ib + k * 36 + ty * 4);
            float4 cv = *(const float4*)(cb + k * 40 + tx * 4);
            float aa[4] = {av.x, av.y, av.z, av.w};
            float cc[4] = {cv.x, cv.y, cv.z, cv.w};
#pragma unroll
            for (int ii = 0; ii < 4; ii++)
#pragma unroll
                for (int jj = 0; jj < 4; jj++)
                    acc[ii][jj] = fmaf(aa[ii], cc[jj], acc[ii][jj]);
        }
        if (c < 31) {
            int nxt = cur ^ 1;
            float* ibn = sh + nxt * 1152;
            float* cbn = sh + 2304 + nxt * 1280;
#pragma unroll
            for (int j = 0; j < 7; j++) {
                int v = tid + j * 96;
                if (v < 608) {
                    float4 t = tmp[j];
                    if (v < 288) {
                        int r = v >> 3, q = v & 7; int k = q * 4;
                        ibn[(k + 0) * 36 + r] = t.x; ibn[(k + 1) * 36 + r] = t.y;
                        ibn[(k + 2) * 36 + r] = t.z; ibn[(k + 3) * 36 + r] = t.w;
                    } else {
                        int v2 = v - 288; int l = v2 >> 3, q = v2 & 7; int k = q * 4;
                        cbn[(k + 0) * 40 + l] = t.x; cbn[(k + 1) * 40 + l] = t.y;
                        cbn[(k + 2) * 40 + l] = t.z; cbn[(k + 3) * 40 + l] = t.w;
                    }
                }
            }
        }
        __syncthreads();
    }

    // ---- phase 2: epilogue (smem re-layout over dead phase-1 buffers) ----
    float* FS = sh;             // 36 x 41 (leaky_relu(S)), later overwritten by i2t attn C
    float* Am = sh + 1476;      // 40 x 37  t2i attention A[l][r]
    float* Ms = sh + 2956;      // 40 x 37 / 36 x 41 scratch (A.G then C.H)
    float* Gs = sh + 4436;      // 36 x 36
    float* Hs = sh + 5732;      // 40 x 40
    float* Pb = sh + 7332;      // 36
    float* Qi = sh + 7368;      // 40
    float* rn = sh + 7408;      // 36
    float* cn = sh + 7444;      // 40
    float* s1 = sh + 7484;      // 40
    float* s2 = sh + 7524;      // 36

    if (act) {
#pragma unroll
        for (int ii = 0; ii < 4; ii++)
#pragma unroll
            for (int jj = 0; jj < 4; jj++) {
                float v = acc[ii][jj];
                v = (v >= 0.f) ? v : 0.1f * v;            // leaky_relu
                FS[(ty * 4 + ii) * 41 + tx * 4 + jj] = v;
            }
    }
    for (int idx = tid; idx < 1296; idx += 96) Gs[idx] = g_G[(size_t)b * 1296 + idx];
    for (int idx = tid; idx < 1600; idx += 96) Hs[idx] = g_H[(size_t)i * 1600 + idx];
    if (tid < 36) Pb[tid] = g_P[(size_t)i * (NB * NR) + b * NR + tid];
    if (tid >= 40 && tid < 80) Qi[tid - 40] = g_Q[(size_t)b * (NB * NL) + i * NL + (tid - 40)];
    __syncthreads();

    if (tid < 36) {                 // row norms over l
        float s = 0.f;
#pragma unroll
        for (int l = 0; l < 40; l++) { float v = FS[tid * 41 + l]; s = fmaf(v, v, s); }
        rn[tid] = sqrtf(s) + EPSF;
    } else if (tid >= 48 && tid < 88) {   // col norms over r
        int l = tid - 48; float s = 0.f;
#pragma unroll
        for (int r = 0; r < 36; r++) { float v = FS[r * 41 + l]; s = fmaf(v, v, s); }
        cn[l] = sqrtf(s) + EPSF;
    }
    __syncthreads();

    if (tid < 40) {                 // t2i attn: softmax over r per word l
        int l = tid;
        float z[36]; float mx = -1e30f;
#pragma unroll
        for (int r = 0; r < 36; r++) { float v = LAMS * FS[r * 41 + l] / rn[r]; z[r] = v; mx = fmaxf(mx, v); }
        float sum = 0.f;
#pragma unroll
        for (int r = 0; r < 36; r++) { float e = expf(z[r] - mx); z[r] = e; sum += e; }
        float inv = 1.f / sum;
#pragma unroll
        for (int r = 0; r < 36; r++) Am[l * 37 + r] = z[r] * inv;
    }
    __syncthreads();

    if (tid < 36) {                 // i2t attn: softmax over l per region r (overwrite FS in place)
        int r = tid;
        float z[40]; float mx = -1e30f;
#pragma unroll
        for (int l = 0; l < 40; l++) { float v = LAMS * FS[r * 41 + l] / cn[l]; z[l] = v; mx = fmaxf(mx, v); }
        float sum = 0.f;
#pragma unroll
        for (int l = 0; l < 40; l++) { float e = expf(z[l] - mx); z[l] = e; sum += e; }
        float inv = 1.f / sum;
#pragma unroll
        for (int l = 0; l < 40; l++) FS[r * 41 + l] = z[l] * inv;
    }
    __syncthreads();

    // Mt[l][r] = sum_r' A[l][r'] G[r'][r]
    for (int idx = tid; idx < 1440; idx += 96) {
        int l = idx / 36, r = idx - l * 36;
        float s = 0.f;
#pragma unroll
        for (int r2 = 0; r2 < 36; r2++) s = fmaf(Am[l * 37 + r2], Gs[r2 * 36 + r], s);
        Ms[l * 37 + r] = s;
    }
    __syncthreads();

    if (tid < 40) {                 // t2i sim per word
        int l = tid; float w12 = 0.f, w2 = 0.f;
#pragma unroll
        for (int r = 0; r < 36; r++) {
            float a = Am[l * 37 + r];
            w12 = fmaf(a, Pb[r], w12);
            w2 = fmaf(a, Ms[l * 37 + r], w2);
        }
        float den = fmaxf(g_w1t[i] * sqrtf(fmaxf(w2, 0.f)), EPSF);
        s1[l] = w12 / den;
    }
    __syncthreads();

    // Mi[r][l] = sum_l' C[r][l'] H[l'][l]   (C lives in FS)
    for (int idx = tid; idx < 1440; idx += 96) {
        int r = idx / 40, l = idx - r * 40;
        float s = 0.f;
#pragma unroll
        for (int l2 = 0; l2 < 40; l2++) s = fmaf(FS[r * 41 + l2], Hs[l2 * 40 + l], s);
        Ms[r * 41 + l] = s;
    }
    __syncthreads();

    if (tid < 36) {                 // i2t sim per region
        int r = tid; float w12 = 0.f, w2 = 0.f;
#pragma unroll
        for (int l = 0; l < 40; l++) {
            float cc = FS[r * 41 + l];
            w12 = fmaf(cc, Qi[l], w12);
            w2 = fmaf(cc, Ms[r * 41 + l], w2);
        }
        float den = fmaxf(g_w1i[b] * sqrtf(fmaxf(w2, 0.f)), EPSF);
        s2[r] = w12 / den;
    }
    __syncthreads();

    if (tid == 0) {
        float m1 = 0.f;
#pragma unroll
        for (int l = 0; l < 40; l++) m1 += s1[l];
        m1 *= (1.f / 40.f);
        float m2 = 0.f;
#pragma unroll
        for (int r = 0; r < 36; r++) m2 += s2[r];
        m2 *= (1.f / 36.f);
        float v1 = logf(expf(m1 * LAML)) / LAML;
        float v2 = logf(expf(m2 * LAML)) / LAML;
        out[(size_t)b * NB + i] = g_base[b * NB + i] + v1 + v2;
    }
}

extern "C" void kernel_launch(void* const* d_in, const int* in_sizes, int n_in,
                              void* d_out, int out_size) {
    (void)in_sizes; (void)n_in; (void)out_size;
    const float* pool_img = (const float*)d_in[0];
    const float* img_emb  = (const float*)d_in[1];
    const float* pool_txt = (const float*)d_in[2];
    const float* cap_emb  = (const float*)d_in[3];
    float* out = (float*)d_out;

    cudaFuncSetAttribute((const void*)gram_kernel,
                         cudaFuncAttributeMaxDynamicSharedMemorySize, NL * ND * 4);

    norm_kernel<<<64, 256>>>(pool_img, pool_txt);
    sgemm_tn<<<dim3((NB * NR) / 64, NB / 64), 256>>>(pool_txt, img_emb, NB, NB * NR, ND, 0);
    sgemm_tn<<<dim3((NB * NL) / 64, NB / 64), 256>>>(pool_img, cap_emb, NB, NB * NL, ND, 1);
    sgemm_tn<<<dim3(NB / 64, NB / 64), 256>>>(pool_img, pool_txt, NB, NB, ND, 2);
    gram_kernel<<<NB, 256, NR * ND * 4>>>(img_emb, NR, 0);
    gram_kernel<<<NB, 256, NL * ND * 4>>>(cap_emb, NL, 1);
    pair_kernel<<<dim3(NB, NB), 96>>>(img_emb, cap_emb, out);
}

// round 3
// speedup vs baseline: 3.7177x; 3.7177x over previous
#include <cuda_runtime.h>
#include <math.h>
#include <cstdint>

#define NB 256
#define NR 36
#define NL 40
#define ND 1024
#define MT (NB * NR)   /* 9216  */
#define NT (NB * NL)   /* 10240 */
#define EPSF 1e-8f
#define LAMS 9.0f

// ---- scratch (device globals; no allocation allowed) ----
__device__ float g_S[(size_t)MT * NT];   // S^T[n][m], leaky-relu'd raw dots (378MB)
__device__ float g_P[NB * NB * NR];      // P[i][b*36+r] = img_emb[b,r] . pool_txt[i]
__device__ float g_Q[NB * NB * NL];      // Q[b][i*40+l] = cap_emb[i,l] . pool_img[b]
__device__ float g_G[NB * NR * NR];      // per-image region Gram
__device__ float g_H[NB * NL * NL];      // per-caption word Gram
__device__ float g_base[NB * NB];        // pool_img @ pool_txt^T
__device__ float g_w1i[NB];
__device__ float g_w1t[NB];

__device__ __forceinline__ float4 ldg4(const float* p) {
    return *reinterpret_cast<const float4*>(p);
}
__device__ __forceinline__ uint32_t f2tf32(float x) {
    uint32_t u;
    asm("cvt.rna.tf32.f32 %0, %1;" : "=r"(u) : "f"(x));
    return u;
}
__device__ __forceinline__ void mma_tf32(float* c, const uint32_t* a, const uint32_t* b) {
    asm volatile(
        "mma.sync.aligned.m16n8k8.row.col.f32.tf32.tf32.f32 "
        "{%0,%1,%2,%3}, {%4,%5,%6,%7}, {%8,%9}, {%0,%1,%2,%3};"
        : "+f"(c[0]), "+f"(c[1]), "+f"(c[2]), "+f"(c[3])
        : "r"(a[0]), "r"(a[1]), "r"(a[2]), "r"(a[3]), "r"(b[0]), "r"(b[1]));
}

// ============================ precompute kernels ============================
__global__ void norm_kernel(const float* __restrict__ pi, const float* __restrict__ pt) {
    int w = blockIdx.x * 8 + (threadIdx.x >> 5);
    int lane = threadIdx.x & 31;
    const float* src = (w < NB) ? (pi + (size_t)w * ND) : (pt + (size_t)(w - NB) * ND);
    float s = 0.f;
    for (int j = lane; j < ND; j += 32) { float v = src[j]; s = fmaf(v, v, s); }
#pragma unroll
    for (int o = 16; o; o >>= 1) s += __shfl_down_sync(0xffffffffu, s, o);
    if (lane == 0) {
        float r = sqrtf(s);
        if (w < NB) g_w1i[w] = r; else g_w1t[w - NB] = r;
    }
}

__global__ void sgemm_tn(const float* __restrict__ A, const float* __restrict__ Bm,
                         int M, int N, int K, int dst) {
    float* C = (dst == 0) ? g_P : (dst == 1) ? g_Q : g_base;
    __shared__ float As[16 * 64];
    __shared__ float Bs[16 * 64];
    int tid = threadIdx.x;
    int tx = tid & 15, ty = tid >> 4;
    int m0 = blockIdx.y * 64, n0 = blockIdx.x * 64;
    int row = tid >> 2, q = tid & 3;
    float acc[4][4] = {};
    for (int k0 = 0; k0 < K; k0 += 16) {
        float4 a = ldg4(A + (size_t)(m0 + row) * K + k0 + q * 4);
        float4 bb = ldg4(Bm + (size_t)(n0 + row) * K + k0 + q * 4);
        As[(q * 4 + 0) * 64 + row] = a.x;  As[(q * 4 + 1) * 64 + row] = a.y;
        As[(q * 4 + 2) * 64 + row] = a.z;  As[(q * 4 + 3) * 64 + row] = a.w;
        Bs[(q * 4 + 0) * 64 + row] = bb.x; Bs[(q * 4 + 1) * 64 + row] = bb.y;
        Bs[(q * 4 + 2) * 64 + row] = bb.z; Bs[(q * 4 + 3) * 64 + row] = bb.w;
        __syncthreads();
#pragma unroll
        for (int k = 0; k < 16; k++) {
            float4 av = *(const float4*)(As + k * 64 + ty * 4);
            float4 bv = *(const float4*)(Bs + k * 64 + tx * 4);
            float aa[4] = {av.x, av.y, av.z, av.w};
            float bw[4] = {bv.x, bv.y, bv.z, bv.w};
#pragma unroll
            for (int ii = 0; ii < 4; ii++)
#pragma unroll
                for (int jj = 0; jj < 4; jj++)
                    acc[ii][jj] = fmaf(aa[ii], bw[jj], acc[ii][jj]);
        }
        __syncthreads();
    }
#pragma unroll
    for (int ii = 0; ii < 4; ii++)
#pragma unroll
        for (int jj = 0; jj < 4; jj++)
            C[(size_t)(m0 + ty * 4 + ii) * N + n0 + tx * 4 + jj] = acc[ii][jj];
}

__global__ void gram_kernel(const float* __restrict__ emb, int ROWS, int which) {
    extern __shared__ float Es[];
    float* out = which ? g_H : g_G;
    int b = blockIdx.x, tid = threadIdx.x;
    int n = ROWS * ND;
    for (int idx = tid; idx < n; idx += 256) Es[idx] = emb[(size_t)b * n + idx];
    __syncthreads();
    int wid = tid >> 5, lane = tid & 31;
    int np = ROWS * ROWS;
    for (int p = wid; p < np; p += 8) {
        int r = p / ROWS, r2 = p - r * ROWS;
        const float* e1 = Es + r * ND;
        const float* e2 = Es + r2 * ND;
        float s = 0.f;
        for (int j = lane; j < ND; j += 32) s = fmaf(e1[j], e2[j], s);
#pragma unroll
        for (int o = 16; o; o >>= 1) s += __shfl_down_sync(0xffffffffu, s, o);
        if (lane == 0) out[(size_t)b * np + p] = s;
    }
}

// ============================ tf32 mma.sync S-GEMM ============================
// S^T[n][m] = leaky_relu( img_emb[m,:] . cap_emb[n,:] )
// BM=128, BN=256, BK=32, 256 threads, warp grid 2x4, warp tile 64x64.
// SMEM: A[m][k] stride 36, B[n][k] stride 36 -> conflict-free LDS & STS.
#define BM 128
#define BN 256
#define BK 32
#define ROWW 36
#define ASZ (BM * ROWW)        /* 4608 floats */
#define BSZ (BN * ROWW)        /* 9216 floats */
#define STAGEF (ASZ + BSZ)     /* 13824 floats */
#define GEMM_SMEM (2 * STAGEF * 4)  /* 110592 bytes */

__global__ void __launch_bounds__(256, 1) s_gemm(const float* __restrict__ A,
                                                 const float* __restrict__ B,
                                                 float* __restrict__ S) {
    extern __shared__ float sm[];
    const int tid = threadIdx.x;
    const int wid = tid >> 5;
    const int lane = tid & 31;
    const int g = lane >> 2;
    const int t = lane & 3;
    const int wm = wid >> 2;       // 0..1
    const int wn = wid & 3;        // 0..3
    const int m0 = blockIdx.y * BM;
    const int n0 = blockIdx.x * BN;

    const float* Ag = A + (size_t)m0 * ND;
    const float* Bg = B + (size_t)n0 * ND;

    // copy-lane geometry (fixed per thread)
    const int arow0 = tid >> 3;          // 0..31  (j adds 32)
    const int brow0 = tid >> 3;          // 0..31  (j adds 32, h adds 128)
    const int qq = tid & 7;              // float4 index within 32-float row chunk

    float cacc[4][8][4];
#pragma unroll
    for (int a = 0; a < 4; a++)
#pragma unroll
        for (int bb = 0; bb < 8; bb++)
#pragma unroll
            for (int cc = 0; cc < 4; cc++) cacc[a][bb][cc] = 0.f;

    float4 ra[2], rb[4];

#define LDG_HALF(kc, h) do {                                                   \
    _Pragma("unroll")                                                          \
    for (int j = 0; j < 2; j++) {                                              \
        int row = (h) * 64 + arow0 + j * 32;                                   \
        ra[j] = ldg4(Ag + (size_t)row * ND + (kc) + qq * 4);                   \
    }                                                                          \
    _Pragma("unroll")                                                          \
    for (int j = 0; j < 4; j++) {                                              \
        int row = (h) * 128 + brow0 + j * 32;                                  \
        rb[j] = ldg4(Bg + (size_t)row * ND + (kc) + qq * 4);                   \
    }                                                                          \
} while (0)

#define STS_HALF(stg, h) do {                                                  \
    float* Ad = sm + (stg) * STAGEF;                                           \
    float* Bd = Ad + ASZ;                                                      \
    _Pragma("unroll")                                                          \
    for (int j = 0; j < 2; j++) {                                              \
        int row = (h) * 64 + arow0 + j * 32;                                   \
        uint4* dst = (uint4*)(Ad + row * ROWW + qq * 4);                       \
        *dst = make_uint4(f2tf32(ra[j].x), f2tf32(ra[j].y),                    \
                          f2tf32(ra[j].z), f2tf32(ra[j].w));                   \
    }                                                                          \
    _Pragma("unroll")                                                          \
    for (int j = 0; j < 4; j++) {                                              \
        int row = (h) * 128 + brow0 + j * 32;                                  \
        uint4* dst = (uint4*)(Bd + row * ROWW + qq * 4);                       \
        *dst = make_uint4(f2tf32(rb[j].x), f2tf32(rb[j].y),                    \
                          f2tf32(rb[j].z), f2tf32(rb[j].w));                   \
    }                                                                          \
} while (0)

#define COMPUTE(stg, ks) do {                                                  \
    const uint32_t* Au = (const uint32_t*)(sm + (stg) * STAGEF);               \
    const uint32_t* Bu = (const uint32_t*)(sm + (stg) * STAGEF + ASZ);         \
    const int ko = (ks) * 8 + t;                                               \
    uint32_t af[4][4];                                                         \
    uint32_t bf[8][2];                                                         \
    _Pragma("unroll")                                                          \
    for (int mt = 0; mt < 4; mt++) {                                           \
        int r0 = wm * 64 + mt * 16 + g;                                        \
        af[mt][0] = Au[r0 * ROWW + ko];                                        \
        af[mt][1] = Au[(r0 + 8) * ROWW + ko];                                  \
        af[mt][2] = Au[r0 * ROWW + ko + 4];                                    \
        af[mt][3] = Au[(r0 + 8) * ROWW + ko + 4];                              \
    }                                                                          \
    _Pragma("unroll")                                                          \
    for (int nt = 0; nt < 8; nt++) {                                           \
        int c0i = wn * 64 + nt * 8 + g;                                        \
        bf[nt][0] = Bu[c0i * ROWW + ko];                                       \
        bf[nt][1] = Bu[c0i * ROWW + ko + 4];                                   \
    }                                                                          \
    _Pragma("unroll")                                                          \
    for (int mt = 0; mt < 4; mt++)                                             \
        _Pragma("unroll")                                                      \
        for (int nt = 0; nt < 8; nt++)                                         \
            mma_tf32(cacc[mt][nt], af[mt], bf[nt]);                            \
} while (0)

    // prologue: chunk 0 -> stage 0
    LDG_HALF(0, 0);
    STS_HALF(0, 0);
    LDG_HALF(0, 1);
    STS_HALF(0, 1);
    __syncthreads();

    int st = 0;
#pragma unroll 1
    for (int c = 0; c < 32; c++) {
        int nst = st ^ 1;
        int kn = (c + 1) * BK;
        bool more = (c < 31);
        if (more) LDG_HALF(kn, 0);
        COMPUTE(st, 0);
        COMPUTE(st, 1);
        if (more) { STS_HALF(nst, 0); LDG_HALF(kn, 1); }
        COMPUTE(st, 2);
        COMPUTE(st, 3);
        if (more) STS_HALF(nst, 1);
        __syncthreads();
        st = nst;
    }

    // epilogue: fused leaky_relu, store S^T[n][m]
#pragma unroll
    for (int mt = 0; mt < 4; mt++) {
        int m = m0 + wm * 64 + mt * 16 + g;
#pragma unroll
        for (int nt = 0; nt < 8; nt++) {
            int n = n0 + wn * 64 + nt * 8 + 2 * t;
            float v0 = cacc[mt][nt][0]; v0 = (v0 >= 0.f) ? v0 : 0.1f * v0;
            float v1 = cacc[mt][nt][1]; v1 = (v1 >= 0.f) ? v1 : 0.1f * v1;
            float v2 = cacc[mt][nt][2]; v2 = (v2 >= 0.f) ? v2 : 0.1f * v2;
            float v3 = cacc[mt][nt][3]; v3 = (v3 >= 0.f) ? v3 : 0.1f * v3;
            __stcs(S + (size_t)n * MT + m, v0);
            __stcs(S + (size_t)(n + 1) * MT + m, v1);
            __stcs(S + (size_t)n * MT + m + 8, v2);
            __stcs(S + (size_t)(n + 1) * MT + m + 8, v3);
        }
    }
#undef LDG_HALF
#undef STS_HALF
#undef COMPUTE
}

// ============================ per-pair epilogue ============================
__global__ void __launch_bounds__(128) pair_epilogue(const float* __restrict__ S,
                                                     float* __restrict__ out) {
    __shared__ __align__(16) float FS[NR * 41];
    __shared__ __align__(16) float Gs[NR * NR];
    __shared__ __align__(16) float Hs[NL * NL];
    __shared__ float Pb[NR], Qi[NL], rnl[NR], cnl[NL], s1s[NL], s2s[NR];
    const int i = blockIdx.x, b = blockIdx.y, tid = threadIdx.x;

    const float* Sp = S + (size_t)i * NL * MT + (size_t)b * NR;
    for (int idx = tid; idx < NR * NL; idx += 128) {
        int l = idx / NR, r = idx - l * NR;
        FS[r * 41 + l] = __ldcs(Sp + (size_t)l * MT + r);
    }
    for (int idx = tid; idx < NR * NR; idx += 128) Gs[idx] = g_G[(size_t)b * (NR * NR) + idx];
    for (int idx = tid; idx < NL * NL; idx += 128) Hs[idx] = g_H[(size_t)i * (NL * NL) + idx];
    if (tid < NR) Pb[tid] = g_P[(size_t)i * (NB * NR) + b * NR + tid];
    else if (tid >= 64 && tid < 64 + NL) Qi[tid - 64] = g_Q[(size_t)b * (NB * NL) + i * NL + (tid - 64)];
    __syncthreads();

    if (tid < NL) {                        // column norms over r -> lambda/cn
        int l = tid; float s = 0.f;
#pragma unroll
        for (int r = 0; r < NR; r++) { float v = FS[r * 41 + l]; s = fmaf(v, v, s); }
        cnl[l] = LAMS / (sqrtf(s) + EPSF);
    } else if (tid >= 64 && tid < 64 + NR) {  // row norms over l -> lambda/rn
        int r = tid - 64; float s = 0.f;
#pragma unroll
        for (int l = 0; l < NL; l++) { float v = FS[r * 41 + l]; s = fmaf(v, v, s); }
        rnl[r] = LAMS / (sqrtf(s) + EPSF);
    }
    __syncthreads();

    if (tid < NL) {                        // t2i: word l (softmax norm cancels)
        int l = tid;
        float a[NR];
        float w12 = 0.f;
#pragma unroll
        for (int r = 0; r < NR; r++) {
            a[r] = __expf(FS[r * 41 + l] * rnl[r]);
            w12 = fmaf(a[r], Pb[r], w12);
        }
        float w2 = 0.f;
#pragma unroll
        for (int r = 0; r < NR; r++) {
            float m = 0.f;
#pragma unroll
            for (int q = 0; q < NR / 4; q++) {
                float4 gg = *(const float4*)(Gs + r * NR + q * 4);
                m = fmaf(gg.x, a[q * 4 + 0], m); m = fmaf(gg.y, a[q * 4 + 1], m);
                m = fmaf(gg.z, a[q * 4 + 2], m); m = fmaf(gg.w, a[q * 4 + 3], m);
            }
            w2 = fmaf(m, a[r], w2);
        }
        float den = fmaxf(g_w1t[i] * sqrtf(fmaxf(w2, 0.f)), EPSF);
        s1s[l] = __fdividef(w12, den);
    } else if (tid >= 64 && tid < 64 + NR) {   // i2t: region r
        int r = tid - 64;
        float cc[NL];
        float w12 = 0.f;
#pragma unroll
        for (int l = 0; l < NL; l++) {
            cc[l] = __expf(FS[r * 41 + l] * cnl[l]);
            w12 = fmaf(cc[l], Qi[l], w12);
        }
        float w2 = 0.f;
#pragma unroll
        for (int l = 0; l < NL; l++) {
            float m = 0.f;
#pragma unroll
            for (int q = 0; q < NL / 4; q++) {
                float4 h = *(const float4*)(Hs + l * NL + q * 4);
                m = fmaf(h.x, cc[q * 4 + 0], m); m = fmaf(h.y, cc[q * 4 + 1], m);
                m = fmaf(h.z, cc[q * 4 + 2], m); m = fmaf(h.w, cc[q * 4 + 3], m);
            }
            w2 = fmaf(m, cc[l], w2);
        }
        float den = fmaxf(g_w1i[b] * sqrtf(fmaxf(w2, 0.f)), EPSF);
        s2s[r] = __fdividef(w12, den);
    }
    __syncthreads();

    if (tid == 0) {
        float m1 = 0.f, m2 = 0.f;
#pragma unroll
        for (int l = 0; l < NL; l++) m1 += s1s[l];
#pragma unroll
        for (int r = 0; r < NR; r++) m2 += s2s[r];
        out[(size_t)b * NB + i] = g_base[b * NB + i] + m1 * (1.f / NL) + m2 * (1.f / NR);
    }
}

// ============================ launch ============================
extern "C" void kernel_launch(void* const* d_in, const int* in_sizes, int n_in,
                              void* d_out, int out_size) {
    (void)in_sizes; (void)n_in; (void)out_size;
    const float* pool_img = (const float*)d_in[0];
    const float* img_emb  = (const float*)d_in[1];
    const float* pool_txt = (const float*)d_in[2];
    const float* cap_emb  = (const float*)d_in[3];
    float* out = (float*)d_out;

    cudaFuncSetAttribute((const void*)gram_kernel,
                         cudaFuncAttributeMaxDynamicSharedMemorySize, NL * ND * 4);
    cudaFuncSetAttribute((const void*)s_gemm,
                         cudaFuncAttributeMaxDynamicSharedMemorySize, GEMM_SMEM);

    float* dS = nullptr;
    cudaGetSymbolAddress((void**)&dS, g_S);

    norm_kernel<<<64, 256>>>(pool_img, pool_txt);
    sgemm_tn<<<dim3((NB * NR) / 64, NB / 64), 256>>>(pool_txt, img_emb, NB, NB * NR, ND, 0);
    sgemm_tn<<<dim3((NB * NL) / 64, NB / 64), 256>>>(pool_img, cap_emb, NB, NB * NL, ND, 1);
    sgemm_tn<<<dim3(NB / 64, NB / 64), 256>>>(pool_img, pool_txt, NB, NB, ND, 2);
    gram_kernel<<<NB, 256, NR * ND * 4>>>(img_emb, NR, 0);
    gram_kernel<<<NB, 256, NL * ND * 4>>>(cap_emb, NL, 1);
    s_gemm<<<dim3(NT / BN, MT / BM), 256, GEMM_SMEM>>>(img_emb, cap_emb, dS);
    pair_epilogue<<<dim3(NB, NB), 128>>>(dS, out);
}

// round 4
// speedup vs baseline: 3.7715x; 1.0145x over previous
#include <cuda_runtime.h>
#include <cuda_bf16.h>
#include <math.h>
#include <cstdint>

#define NB 256
#define NR 36
#define NL 40
#define ND 1024
#define MT (NB * NR)   /* 9216  */
#define NT (NB * NL)   /* 10240 */
#define EPSF 1e-8f
#define LAMS 9.0f

// ---- scratch (device globals; no allocation allowed) ----
__device__ float g_S[(size_t)MT * NT];   // S^T[n][m], leaky-relu'd raw dots (378MB)
__device__ float g_P[NB * NB * NR];      // P[i][b*36+r] = img_emb[b,r] . pool_txt[i]
__device__ float g_Q[NB * NB * NL];      // Q[b][i*40+l] = cap_emb[i,l] . pool_img[b]
__device__ float g_G[NB * NR * NR];      // per-image region Gram
__device__ float g_H[NB * NL * NL];      // per-caption word Gram
__device__ float g_base[NB * NB];        // pool_img @ pool_txt^T
__device__ float g_w1i[NB];
__device__ float g_w1t[NB];

__device__ __forceinline__ float4 ldg4(const float* p) {
    return *reinterpret_cast<const float4*>(p);
}
__device__ __forceinline__ uint32_t pack_bf2(float x, float y) {
    __nv_bfloat162 h = __float22bfloat162_rn(make_float2(x, y));
    return *reinterpret_cast<uint32_t*>(&h);
}
__device__ __forceinline__ void mma_bf16(float* c, const uint32_t* a, const uint32_t* b) {
    asm volatile(
        "mma.sync.aligned.m16n8k16.row.col.f32.bf16.bf16.f32 "
        "{%0,%1,%2,%3}, {%4,%5,%6,%7}, {%8,%9}, {%0,%1,%2,%3};"
        : "+f"(c[0]), "+f"(c[1]), "+f"(c[2]), "+f"(c[3])
        : "r"(a[0]), "r"(a[1]), "r"(a[2]), "r"(a[3]), "r"(b[0]), "r"(b[1]));
}

// ============================ precompute kernels ============================
__global__ void norm_kernel(const float* __restrict__ pi, const float* __restrict__ pt) {
    int w = blockIdx.x * 8 + (threadIdx.x >> 5);
    int lane = threadIdx.x & 31;
    const float* src = (w < NB) ? (pi + (size_t)w * ND) : (pt + (size_t)(w - NB) * ND);
    float s = 0.f;
    for (int j = lane; j < ND; j += 32) { float v = src[j]; s = fmaf(v, v, s); }
#pragma unroll
    for (int o = 16; o; o >>= 1) s += __shfl_down_sync(0xffffffffu, s, o);
    if (lane == 0) {
        float r = sqrtf(s);
        if (w < NB) g_w1i[w] = r; else g_w1t[w - NB] = r;
    }
}

__global__ void sgemm_tn(const float* __restrict__ A, const float* __restrict__ Bm,
                         int M, int N, int K, int dst) {
    float* C = (dst == 0) ? g_P : (dst == 1) ? g_Q : g_base;
    __shared__ float As[16 * 64];
    __shared__ float Bs[16 * 64];
    int tid = threadIdx.x;
    int tx = tid & 15, ty = tid >> 4;
    int m0 = blockIdx.y * 64, n0 = blockIdx.x * 64;
    int row = tid >> 2, q = tid & 3;
    float acc[4][4] = {};
    for (int k0 = 0; k0 < K; k0 += 16) {
        float4 a = ldg4(A + (size_t)(m0 + row) * K + k0 + q * 4);
        float4 bb = ldg4(Bm + (size_t)(n0 + row) * K + k0 + q * 4);
        As[(q * 4 + 0) * 64 + row] = a.x;  As[(q * 4 + 1) * 64 + row] = a.y;
        As[(q * 4 + 2) * 64 + row] = a.z;  As[(q * 4 + 3) * 64 + row] = a.w;
        Bs[(q * 4 + 0) * 64 + row] = bb.x; Bs[(q * 4 + 1) * 64 + row] = bb.y;
        Bs[(q * 4 + 2) * 64 + row] = bb.z; Bs[(q * 4 + 3) * 64 + row] = bb.w;
        __syncthreads();
#pragma unroll
        for (int k = 0; k < 16; k++) {
            float4 av = *(const float4*)(As + k * 64 + ty * 4);
            float4 bv = *(const float4*)(Bs + k * 64 + tx * 4);
            float aa[4] = {av.x, av.y, av.z, av.w};
            float bw[4] = {bv.x, bv.y, bv.z, bv.w};
#pragma unroll
            for (int ii = 0; ii < 4; ii++)
#pragma unroll
                for (int jj = 0; jj < 4; jj++)
                    acc[ii][jj] = fmaf(aa[ii], bw[jj], acc[ii][jj]);
        }
        __syncthreads();
    }
#pragma unroll
    for (int ii = 0; ii < 4; ii++)
#pragma unroll
        for (int jj = 0; jj < 4; jj++)
            C[(size_t)(m0 + ty * 4 + ii) * N + n0 + tx * 4 + jj] = acc[ii][jj];
}

__global__ void gram_kernel(const float* __restrict__ emb, int ROWS, int which) {
    extern __shared__ float Es[];
    float* out = which ? g_H : g_G;
    int b = blockIdx.x, tid = threadIdx.x;
    int n = ROWS * ND;
    for (int idx = tid; idx < n; idx += 256) Es[idx] = emb[(size_t)b * n + idx];
    __syncthreads();
    int wid = tid >> 5, lane = tid & 31;
    int np = ROWS * ROWS;
    for (int p = wid; p < np; p += 8) {
        int r = p / ROWS, r2 = p - r * ROWS;
        const float* e1 = Es + r * ND;
        const float* e2 = Es + r2 * ND;
        float s = 0.f;
        for (int j = lane; j < ND; j += 32) s = fmaf(e1[j], e2[j], s);
#pragma unroll
        for (int o = 16; o; o >>= 1) s += __shfl_down_sync(0xffffffffu, s, o);
        if (lane == 0) out[(size_t)b * np + p] = s;
    }
}

// ============================ bf16 mma.sync S-GEMM ============================
// S^T[n][m] = leaky_relu( img_emb[m,:] . cap_emb[n,:] )
// BM=128, BN=256, BK=32, 256 threads, warp grid 2x4, warp tile 64x64, m16n8k16.
// SMEM (bf16): A[m][k] stride 40 halfs, B[n][k] stride 40 halfs (20 words).
#define BM 128
#define BN 256
#define BK 32
#define ASZW (BM * 20)          /* 2560 words */
#define BSZW (BN * 20)          /* 5120 words */
#define STAGEW (ASZW + BSZW)    /* 7680 words = 30720 B */
#define GEMM_SMEM (2 * STAGEW * 4)  /* 61440 bytes */

__global__ void __launch_bounds__(256, 1) s_gemm(const float* __restrict__ A,
                                                 const float* __restrict__ B,
                                                 float* __restrict__ S) {
    extern __shared__ uint32_t smw[];
    const int tid = threadIdx.x;
    const int wid = tid >> 5;
    const int lane = tid & 31;
    const int g = lane >> 2;
    const int t = lane & 3;
    const int wm = wid >> 2;       // 0..1
    const int wn = wid & 3;        // 0..3
    const int m0 = blockIdx.y * BM;
    const int n0 = blockIdx.x * BN;

    const float* Ag = A + (size_t)m0 * ND;
    const float* Bg = B + (size_t)n0 * ND;

    const int row0 = tid >> 3;     // 0..31
    const int qq = tid & 7;        // float4 index within 32-float row chunk

    float cacc[4][8][4];
#pragma unroll
    for (int a = 0; a < 4; a++)
#pragma unroll
        for (int bb = 0; bb < 8; bb++)
#pragma unroll
            for (int cc = 0; cc < 4; cc++) cacc[a][bb][cc] = 0.f;

    float4 ra[4], rb[8];

#define LDG_CHUNK(kc) do {                                                     \
    _Pragma("unroll")                                                          \
    for (int j = 0; j < 4; j++)                                                \
        ra[j] = ldg4(Ag + (size_t)(row0 + j * 32) * ND + (kc) + qq * 4);       \
    _Pragma("unroll")                                                          \
    for (int j = 0; j < 8; j++)                                                \
        rb[j] = ldg4(Bg + (size_t)(row0 + j * 32) * ND + (kc) + qq * 4);       \
} while (0)

#define CVT_STS(stg) do {                                                      \
    uint32_t* Ad = smw + (stg) * STAGEW;                                       \
    uint32_t* Bd = Ad + ASZW;                                                  \
    _Pragma("unroll")                                                          \
    for (int j = 0; j < 4; j++) {                                              \
        uint2* dst = (uint2*)(Ad + (row0 + j * 32) * 20 + qq * 2);             \
        *dst = make_uint2(pack_bf2(ra[j].x, ra[j].y), pack_bf2(ra[j].z, ra[j].w)); \
    }                                                                          \
    _Pragma("unroll")                                                          \
    for (int j = 0; j < 8; j++) {                                              \
        uint2* dst = (uint2*)(Bd + (row0 + j * 32) * 20 + qq * 2);             \
        *dst = make_uint2(pack_bf2(rb[j].x, rb[j].y), pack_bf2(rb[j].z, rb[j].w)); \
    }                                                                          \
} while (0)

#define COMPUTE(stg, ks) do {                                                  \
    const uint32_t* Aw = smw + (stg) * STAGEW;                                 \
    const uint32_t* Bw = Aw + ASZW;                                            \
    const int kw = (ks) * 8 + t;                                               \
    uint32_t af[4][4];                                                         \
    uint32_t bf[8][2];                                                         \
    _Pragma("unroll")                                                          \
    for (int mt = 0; mt < 4; mt++) {                                           \
        int r0 = (wm * 64 + mt * 16 + g) * 20;                                 \
        af[mt][0] = Aw[r0 + kw];                                               \
        af[mt][1] = Aw[r0 + 160 + kw];                                         \
        af[mt][2] = Aw[r0 + kw + 4];                                           \
        af[mt][3] = Aw[r0 + 160 + kw + 4];                                     \
    }                                                                          \
    _Pragma("unroll")                                                          \
    for (int nt = 0; nt < 8; nt++) {                                           \
        int c0 = (wn * 64 + nt * 8 + g) * 20;                                  \
        bf[nt][0] = Bw[c0 + kw];                                               \
        bf[nt][1] = Bw[c0 + kw + 4];                                           \
    }                                                                          \
    _Pragma("unroll")                                                          \
    for (int mt = 0; mt < 4; mt++)                                             \
        _Pragma("unroll")                                                      \
        for (int nt = 0; nt < 8; nt++)                                         \
            mma_bf16(cacc[mt][nt], af[mt], bf[nt]);                            \
} while (0)

    // prologue: chunk 0 -> stage 0
    LDG_CHUNK(0);
    CVT_STS(0);
    __syncthreads();

    int st = 0;
#pragma unroll 1
    for (int c = 0; c < 32; c++) {
        int nst = st ^ 1;
        bool more = (c < 31);
        if (more) LDG_CHUNK((c + 1) * BK);
        COMPUTE(st, 0);
        COMPUTE(st, 1);
        if (more) CVT_STS(nst);
        __syncthreads();
        st = nst;
    }

    // epilogue: fused leaky_relu, store S^T[n][m]
#pragma unroll
    for (int mt = 0; mt < 4; mt++) {
        int m = m0 + wm * 64 + mt * 16 + g;
#pragma unroll
        for (int nt = 0; nt < 8; nt++) {
            int n = n0 + wn * 64 + nt * 8 + 2 * t;
            float v0 = cacc[mt][nt][0]; v0 = (v0 >= 0.f) ? v0 : 0.1f * v0;
            float v1 = cacc[mt][nt][1]; v1 = (v1 >= 0.f) ? v1 : 0.1f * v1;
            float v2 = cacc[mt][nt][2]; v2 = (v2 >= 0.f) ? v2 : 0.1f * v2;
            float v3 = cacc[mt][nt][3]; v3 = (v3 >= 0.f) ? v3 : 0.1f * v3;
            __stcs(S + (size_t)n * MT + m, v0);
            __stcs(S + (size_t)(n + 1) * MT + m, v1);
            __stcs(S + (size_t)n * MT + m + 8, v2);
            __stcs(S + (size_t)(n + 1) * MT + m + 8, v3);
        }
    }
#undef LDG_CHUNK
#undef CVT_STS
#undef COMPUTE
}

// ============================ per-pair epilogue (parallelized) ============================
// shared layout (word offsets into sh[]):
//   FS   @ 0     (36x41 = 1476; region sized 1600, reused by M1 [40x40])
//   Am   @ 1600  (40x37 = 1480)   a[l][r] = exp(FS*rnl)
//   Cm   @ 3080  (36x41 = 1476)   c[r][l] = exp(FS*cnl)
//   M2   @ 4556  (36x40 = 1440)   C.H
//   Gs   @ 5996  (36x36 = 1296)
//   Hs   @ 7292  (40x40 = 1600)
//   total 8892 floats
__global__ void __launch_bounds__(128) pair_epilogue(const float* __restrict__ S,
                                                     float* __restrict__ out) {
    __shared__ __align__(16) float sh[8892];
    __shared__ float Pb[NR], Qi[NL], rnl[NR], cnl[NL], s1s[NL], s2s[NR];
    float* FS = sh;
    float* M1 = sh;            // aliases FS (FS dead before M1 written)
    float* Am = sh + 1600;
    float* Cm = sh + 3080;
    float* M2 = sh + 4556;
    float* Gs = sh + 5996;
    float* Hs = sh + 7292;
    const int i = blockIdx.x, b = blockIdx.y, tid = threadIdx.x;

    const float* Sp = S + (size_t)i * NL * MT + (size_t)b * NR;
    for (int idx = tid; idx < NR * NL; idx += 128) {
        int l = idx / NR, r = idx - l * NR;
        FS[r * 41 + l] = __ldcs(Sp + (size_t)l * MT + r);
    }
    for (int idx = tid; idx < NR * NR; idx += 128) Gs[idx] = g_G[(size_t)b * (NR * NR) + idx];
    for (int idx = tid; idx < NL * NL; idx += 128) Hs[idx] = g_H[(size_t)i * (NL * NL) + idx];
    if (tid < NR) Pb[tid] = g_P[(size_t)i * (NB * NR) + b * NR + tid];
    else if (tid >= 64 && tid < 64 + NL) Qi[tid - 64] = g_Q[(size_t)b * (NB * NL) + i * NL + (tid - 64)];
    __syncthreads();

    if (tid < NL) {                        // column norms over r -> lambda/cn
        int l = tid; float s = 0.f;
#pragma unroll
        for (int r = 0; r < NR; r++) { float v = FS[r * 41 + l]; s = fmaf(v, v, s); }
        cnl[l] = LAMS / (sqrtf(s) + EPSF);
    } else if (tid >= 64 && tid < 64 + NR) {  // row norms over l -> lambda/rn
        int r = tid - 64; float s = 0.f;
#pragma unroll
        for (int l = 0; l < NL; l++) { float v = FS[r * 41 + l]; s = fmaf(v, v, s); }
        rnl[r] = LAMS / (sqrtf(s) + EPSF);
    }
    __syncthreads();

    // exp matrices: both directions from the same FS element
    for (int idx = tid; idx < NR * NL; idx += 128) {
        int r = idx / NL, l = idx - r * NL;
        float v = FS[r * 41 + l];
        Am[l * 37 + r] = __expf(v * rnl[r]);
        Cm[r * 41 + l] = __expf(v * cnl[l]);
    }
    __syncthreads();   // FS fully consumed; M1 may now overwrite it

    // M1[l][r(4)] = sum_r' Am[l][r'] * G[r'][r..r+3]   (360 float4 tasks)
    for (int task = tid; task < NL * 9; task += 128) {
        int l = task / 9, rg = task - l * 9;
        float a0 = 0.f, a1 = 0.f, a2 = 0.f, a3 = 0.f;
#pragma unroll
        for (int rp = 0; rp < NR; rp++) {
            float s = Am[l * 37 + rp];
            float4 gv = *(const float4*)(Gs + rp * NR + rg * 4);
            a0 = fmaf(s, gv.x, a0); a1 = fmaf(s, gv.y, a1);
            a2 = fmaf(s, gv.z, a2); a3 = fmaf(s, gv.w, a3);
        }
        *(float4*)(M1 + l * 40 + rg * 4) = make_float4(a0, a1, a2, a3);
    }
    // M2[r][l(4)] = sum_l' Cm[r][l'] * H[l'][l..l+3]   (360 float4 tasks)
    for (int task = tid; task < NR * 10; task += 128) {
        int r = task / 10, lg = task - r * 10;
        float a0 = 0.f, a1 = 0.f, a2 = 0.f, a3 = 0.f;
#pragma unroll
        for (int lp = 0; lp < NL; lp++) {
            float s = Cm[r * 41 + lp];
            float4 hv = *(const float4*)(Hs + lp * NL + lg * 4);
            a0 = fmaf(s, hv.x, a0); a1 = fmaf(s, hv.y, a1);
            a2 = fmaf(s, hv.z, a2); a3 = fmaf(s, hv.w, a3);
        }
        *(float4*)(M2 + r * 40 + lg * 4) = make_float4(a0, a1, a2, a3);
    }
    __syncthreads();

    if (tid < NL) {                        // t2i: word l (softmax norm cancels)
        int l = tid; float w12 = 0.f, w2 = 0.f;
#pragma unroll
        for (int r = 0; r < NR; r++) {
            float a = Am[l * 37 + r];
            w12 = fmaf(a, Pb[r], w12);
            w2 = fmaf(a, M1[l * 40 + r], w2);
        }
        float den = fmaxf(g_w1t[i] * sqrtf(fmaxf(w2, 0.f)), EPSF);
        s1s[l] = __fdividef(w12, den);
    } else if (tid >= 64 && tid < 64 + NR) {   // i2t: region r
        int r = tid - 64; float w12 = 0.f, w2 = 0.f;
#pragma unroll
        for (int l = 0; l < NL; l++) {
            float cc = Cm[r * 41 + l];
            w12 = fmaf(cc, Qi[l], w12);
            w2 = fmaf(cc, M2[r * 40 + l], w2);
        }
        float den = fmaxf(g_w1i[b] * sqrtf(fmaxf(w2, 0.f)), EPSF);
        s2s[r] = __fdividef(w12, den);
    }
    __syncthreads();

    if (tid == 0) {
        float m1 = 0.f, m2 = 0.f;
#pragma unroll
        for (int l = 0; l < NL; l++) m1 += s1s[l];
#pragma unroll
        for (int r = 0; r < NR; r++) m2 += s2s[r];
        out[(size_t)b * NB + i] = g_base[b * NB + i] + m1 * (1.f / NL) + m2 * (1.f / NR);
    }
}

// ============================ launch ============================
extern "C" void kernel_launch(void* const* d_in, const int* in_sizes, int n_in,
                              void* d_out, int out_size) {
    (void)in_sizes; (void)n_in; (void)out_size;
    const float* pool_img = (const float*)d_in[0];
    const float* img_emb  = (const float*)d_in[1];
    const float* pool_txt = (const float*)d_in[2];
    const float* cap_emb  = (const float*)d_in[3];
    float* out = (float*)d_out;

    cudaFuncSetAttribute((const void*)gram_kernel,
                         cudaFuncAttributeMaxDynamicSharedMemorySize, NL * ND * 4);
    cudaFuncSetAttribute((const void*)s_gemm,
                         cudaFuncAttributeMaxDynamicSharedMemorySize, GEMM_SMEM);

    float* dS = nullptr;
    cudaGetSymbolAddress((void**)&dS, g_S);

    // order chosen so s_gemm sits at launch index 3 (the ncu-profiled slot)
    norm_kernel<<<64, 256>>>(pool_img, pool_txt);
    gram_kernel<<<NB, 256, NR * ND * 4>>>(img_emb, NR, 0);
    gram_kernel<<<NB, 256, NL * ND * 4>>>(cap_emb, NL, 1);
    s_gemm<<<dim3(NT / BN, MT / BM), 256, GEMM_SMEM>>>(img_emb, cap_emb, dS);
    sgemm_tn<<<dim3((NB * NR) / 64, NB / 64), 256>>>(pool_txt, img_emb, NB, NB * NR, ND, 0);
    sgemm_tn<<<dim3((NB * NL) / 64, NB / 64), 256>>>(pool_img, cap_emb, NB, NB * NL, ND, 1);
    sgemm_tn<<<dim3(NB / 64, NB / 64), 256>>>(pool_img, pool_txt, NB, NB, ND, 2);
    pair_epilogue<<<dim3(NB, NB), 128>>>(dS, out);
}

// round 5
// speedup vs baseline: 5.3078x; 1.4073x over previous
#include <cuda_runtime.h>
#include <cuda_bf16.h>
#include <math.h>
#include <cstdint>

#define NB 256
#define NR 36
#define NL 40
#define ND 1024
#define MT (NB * NR)   /* 9216  */
#define NT (NB * NL)   /* 10240 */
#define EPSF 1e-8f
#define LAMS 9.0f

// ---- scratch (device globals; no allocation allowed) ----
__device__ float g_S[(size_t)MT * NT];   // S^T[n][m], leaky-relu'd raw dots (378MB)
__device__ float g_P[NB * NB * NR];      // P[i][b*36+r] = img_emb[b,r] . pool_txt[i]
__device__ float g_Q[NB * NB * NL];      // Q[b][i*40+l] = cap_emb[i,l] . pool_img[b]
__device__ float g_G[NB * NR * NR];      // per-image region Gram
__device__ float g_H[NB * NL * NL];      // per-caption word Gram
__device__ float g_base[NB * NB];        // pool_img @ pool_txt^T
__device__ float g_w1i[NB];
__device__ float g_w1t[NB];

__device__ __forceinline__ float4 ldg4(const float* p) {
    return *reinterpret_cast<const float4*>(p);
}
__device__ __forceinline__ uint32_t pack_bf2(float x, float y) {
    __nv_bfloat162 h = __float22bfloat162_rn(make_float2(x, y));
    return *reinterpret_cast<uint32_t*>(&h);
}
__device__ __forceinline__ void mma_bf16(float* c, const uint32_t* a, const uint32_t* b) {
    asm volatile(
        "mma.sync.aligned.m16n8k16.row.col.f32.bf16.bf16.f32 "
        "{%0,%1,%2,%3}, {%4,%5,%6,%7}, {%8,%9}, {%0,%1,%2,%3};"
        : "+f"(c[0]), "+f"(c[1]), "+f"(c[2]), "+f"(c[3])
        : "r"(a[0]), "r"(a[1]), "r"(a[2]), "r"(a[3]), "r"(b[0]), "r"(b[1]));
}

// ============================ precompute kernels ============================
__global__ void norm_kernel(const float* __restrict__ pi, const float* __restrict__ pt) {
    int w = blockIdx.x * 8 + (threadIdx.x >> 5);
    int lane = threadIdx.x & 31;
    const float* src = (w < NB) ? (pi + (size_t)w * ND) : (pt + (size_t)(w - NB) * ND);
    float s = 0.f;
    for (int j = lane; j < ND; j += 32) { float v = src[j]; s = fmaf(v, v, s); }
#pragma unroll
    for (int o = 16; o; o >>= 1) s += __shfl_down_sync(0xffffffffu, s, o);
    if (lane == 0) {
        float r = sqrtf(s);
        if (w < NB) g_w1i[w] = r; else g_w1t[w - NB] = r;
    }
}

// fp32 base gemm only (dst==2 path kept; P/Q now folded into s_gemm)
__global__ void sgemm_tn(const float* __restrict__ A, const float* __restrict__ Bm,
                         int M, int N, int K) {
    float* C = g_base;
    __shared__ float As[16 * 64];
    __shared__ float Bs[16 * 64];
    int tid = threadIdx.x;
    int tx = tid & 15, ty = tid >> 4;
    int m0 = blockIdx.y * 64, n0 = blockIdx.x * 64;
    int row = tid >> 2, q = tid & 3;
    float acc[4][4] = {};
    for (int k0 = 0; k0 < K; k0 += 16) {
        float4 a = ldg4(A + (size_t)(m0 + row) * K + k0 + q * 4);
        float4 bb = ldg4(Bm + (size_t)(n0 + row) * K + k0 + q * 4);
        As[(q * 4 + 0) * 64 + row] = a.x;  As[(q * 4 + 1) * 64 + row] = a.y;
        As[(q * 4 + 2) * 64 + row] = a.z;  As[(q * 4 + 3) * 64 + row] = a.w;
        Bs[(q * 4 + 0) * 64 + row] = bb.x; Bs[(q * 4 + 1) * 64 + row] = bb.y;
        Bs[(q * 4 + 2) * 64 + row] = bb.z; Bs[(q * 4 + 3) * 64 + row] = bb.w;
        __syncthreads();
#pragma unroll
        for (int k = 0; k < 16; k++) {
            float4 av = *(const float4*)(As + k * 64 + ty * 4);
            float4 bv = *(const float4*)(Bs + k * 64 + tx * 4);
            float aa[4] = {av.x, av.y, av.z, av.w};
            float bw[4] = {bv.x, bv.y, bv.z, bv.w};
#pragma unroll
            for (int ii = 0; ii < 4; ii++)
#pragma unroll
                for (int jj = 0; jj < 4; jj++)
                    acc[ii][jj] = fmaf(aa[ii], bw[jj], acc[ii][jj]);
        }
        __syncthreads();
    }
#pragma unroll
    for (int ii = 0; ii < 4; ii++)
#pragma unroll
        for (int jj = 0; jj < 4; jj++)
            C[(size_t)(m0 + ty * 4 + ii) * N + n0 + tx * 4 + jj] = acc[ii][jj];
}

__global__ void gram_kernel(const float* __restrict__ emb, int ROWS, int which) {
    extern __shared__ float Es[];
    float* out = which ? g_H : g_G;
    int b = blockIdx.x, tid = threadIdx.x;
    int n = ROWS * ND;
    for (int idx = tid; idx < n; idx += 256) Es[idx] = emb[(size_t)b * n + idx];
    __syncthreads();
    int wid = tid >> 5, lane = tid & 31;
    int np = ROWS * ROWS;
    for (int p = wid; p < np; p += 8) {
        int r = p / ROWS, r2 = p - r * ROWS;
        const float* e1 = Es + r * ND;
        const float* e2 = Es + r2 * ND;
        float s = 0.f;
        for (int j = lane; j < ND; j += 32) s = fmaf(e1[j], e2[j], s);
#pragma unroll
        for (int o = 16; o; o >>= 1) s += __shfl_down_sync(0xffffffffu, s, o);
        if (lane == 0) out[(size_t)b * np + p] = s;
    }
}

// ============================ bf16 mma.sync folded GEMM ============================
// Augmented GEMM: rows = img_emb(9216) ++ pool_img(256); cols = cap_emb(10240) ++ pool_txt(256)
//  - interior block  -> S^T[n][m] = leaky_relu(dot)
//  - bx==40 (ptxt)   -> g_P[i*MT + m]   (raw)
//  - by>=72 (pimg)   -> g_Q[b*NT + n]   (raw)
//  - corner          -> discarded (base computed in fp32 separately)
#define BM 128
#define BN 256
#define BK 32
#define ASZW (BM * 20)          /* 2560 words */
#define BSZW (BN * 20)          /* 5120 words */
#define STAGEW (ASZW + BSZW)    /* 7680 words = 30720 B */
#define GEMM_SMEM (2 * STAGEW * 4)  /* 61440 bytes */

__global__ void __launch_bounds__(256, 1) s_gemm(const float* __restrict__ img,
                                                 const float* __restrict__ cap,
                                                 const float* __restrict__ pimg,
                                                 const float* __restrict__ ptxt,
                                                 float* __restrict__ S) {
    extern __shared__ uint32_t smw[];
    const int tid = threadIdx.x;
    const int wid = tid >> 5;
    const int lane = tid & 31;
    const int g = lane >> 2;
    const int t = lane & 3;
    const int wm = wid >> 2;       // 0..1
    const int wn = wid & 3;        // 0..3
    const int by = blockIdx.y;
    const int bx = blockIdx.x;
    const int m0 = by * BM;
    const int n0 = bx * BN;
    const bool pBlk = (bx == 40);
    const bool qBlk = (by >= 72);

    const float* Ag = qBlk ? (pimg + (size_t)(by - 72) * BM * ND)
                           : (img + (size_t)m0 * ND);
    const float* Bg = pBlk ? ptxt : (cap + (size_t)n0 * ND);

    const int row0 = tid >> 3;     // 0..31
    const int qq = tid & 7;        // float4 index within 32-float row chunk

    float cacc[4][8][4];
#pragma unroll
    for (int a = 0; a < 4; a++)
#pragma unroll
        for (int bb = 0; bb < 8; bb++)
#pragma unroll
            for (int cc = 0; cc < 4; cc++) cacc[a][bb][cc] = 0.f;

    float4 ra[4], rb[8];

#define LDG_CHUNK(kc) do {                                                     \
    _Pragma("unroll")                                                          \
    for (int j = 0; j < 4; j++)                                                \
        ra[j] = ldg4(Ag + (size_t)(row0 + j * 32) * ND + (kc) + qq * 4);       \
    _Pragma("unroll")                                                          \
    for (int j = 0; j < 8; j++)                                                \
        rb[j] = ldg4(Bg + (size_t)(row0 + j * 32) * ND + (kc) + qq * 4);       \
} while (0)

#define CVT_STS(stg) do {                                                      \
    uint32_t* Ad = smw + (stg) * STAGEW;                                       \
    uint32_t* Bd = Ad + ASZW;                                                  \
    _Pragma("unroll")                                                          \
    for (int j = 0; j < 4; j++) {                                              \
        uint2* dst = (uint2*)(Ad + (row0 + j * 32) * 20 + qq * 2);             \
        *dst = make_uint2(pack_bf2(ra[j].x, ra[j].y), pack_bf2(ra[j].z, ra[j].w)); \
    }                                                                          \
    _Pragma("unroll")                                                          \
    for (int j = 0; j < 8; j++) {                                              \
        uint2* dst = (uint2*)(Bd + (row0 + j * 32) * 20 + qq * 2);             \
        *dst = make_uint2(pack_bf2(rb[j].x, rb[j].y), pack_bf2(rb[j].z, rb[j].w)); \
    }                                                                          \
} while (0)

#define COMPUTE(stg, ks) do {                                                  \
    const uint32_t* Aw = smw + (stg) * STAGEW;                                 \
    const uint32_t* Bw = Aw + ASZW;                                            \
    const int kw = (ks) * 8 + t;                                               \
    uint32_t af[4][4];                                                         \
    uint32_t bf[8][2];                                                         \
    _Pragma("unroll")                                                          \
    for (int mt = 0; mt < 4; mt++) {                                           \
        int r0 = (wm * 64 + mt * 16 + g) * 20;                                 \
        af[mt][0] = Aw[r0 + kw];                                               \
        af[mt][1] = Aw[r0 + 160 + kw];                                         \
        af[mt][2] = Aw[r0 + kw + 4];                                           \
        af[mt][3] = Aw[r0 + 160 + kw + 4];                                     \
    }                                                                          \
    _Pragma("unroll")                                                          \
    for (int nt = 0; nt < 8; nt++) {                                           \
        int c0 = (wn * 64 + nt * 8 + g) * 20;                                  \
        bf[nt][0] = Bw[c0 + kw];                                               \
        bf[nt][1] = Bw[c0 + kw + 4];                                           \
    }                                                                          \
    _Pragma("unroll")                                                          \
    for (int mt = 0; mt < 4; mt++)                                             \
        _Pragma("unroll")                                                      \
        for (int nt = 0; nt < 8; nt++)                                         \
            mma_bf16(cacc[mt][nt], af[mt], bf[nt]);                            \
} while (0)

    // prologue: chunk 0 -> stage 0
    LDG_CHUNK(0);
    CVT_STS(0);
    __syncthreads();

    int st = 0;
#pragma unroll 1
    for (int c = 0; c < 32; c++) {
        int nst = st ^ 1;
        bool more = (c < 31);
        if (more) LDG_CHUNK((c + 1) * BK);
        COMPUTE(st, 0);
        COMPUTE(st, 1);
        if (more) CVT_STS(nst);
        __syncthreads();
        st = nst;
    }

    if (pBlk && qBlk) return;   // corner (pool x pool) discarded

    if (!pBlk && !qBlk) {
        // interior: fused leaky_relu, store S^T[n][m]
#pragma unroll
        for (int mt = 0; mt < 4; mt++) {
            int m = m0 + wm * 64 + mt * 16 + g;
#pragma unroll
            for (int nt = 0; nt < 8; nt++) {
                int n = n0 + wn * 64 + nt * 8 + 2 * t;
                float v0 = cacc[mt][nt][0]; v0 = (v0 >= 0.f) ? v0 : 0.1f * v0;
                float v1 = cacc[mt][nt][1]; v1 = (v1 >= 0.f) ? v1 : 0.1f * v1;
                float v2 = cacc[mt][nt][2]; v2 = (v2 >= 0.f) ? v2 : 0.1f * v2;
                float v3 = cacc[mt][nt][3]; v3 = (v3 >= 0.f) ? v3 : 0.1f * v3;
                __stcs(S + (size_t)n * MT + m, v0);
                __stcs(S + (size_t)(n + 1) * MT + m, v1);
                __stcs(S + (size_t)n * MT + m + 8, v2);
                __stcs(S + (size_t)(n + 1) * MT + m + 8, v3);
            }
        }
    } else if (pBlk) {
        // P block: n indexes pool_txt (i = n - 10240); raw values
#pragma unroll
        for (int mt = 0; mt < 4; mt++) {
            int m = m0 + wm * 64 + mt * 16 + g;
#pragma unroll
            for (int nt = 0; nt < 8; nt++) {
                int i = wn * 64 + nt * 8 + 2 * t;   // n0 local = 0..255
                __stcs(g_P + (size_t)i * MT + m, cacc[mt][nt][0]);
                __stcs(g_P + (size_t)(i + 1) * MT + m, cacc[mt][nt][1]);
                __stcs(g_P + (size_t)i * MT + m + 8, cacc[mt][nt][2]);
                __stcs(g_P + (size_t)(i + 1) * MT + m + 8, cacc[mt][nt][3]);
            }
        }
    } else {
        // Q block: m indexes pool_img (b = m - 9216); raw values
#pragma unroll
        for (int mt = 0; mt < 4; mt++) {
            int b = (by - 72) * BM + wm * 64 + mt * 16 + g;
#pragma unroll
            for (int nt = 0; nt < 8; nt++) {
                int n = n0 + wn * 64 + nt * 8 + 2 * t;
                __stcs(g_Q + (size_t)b * NT + n, cacc[mt][nt][0]);
                __stcs(g_Q + (size_t)b * NT + n + 1, cacc[mt][nt][1]);
                __stcs(g_Q + (size_t)(b + 8) * NT + n, cacc[mt][nt][2]);
                __stcs(g_Q + (size_t)(b + 8) * NT + n + 1, cacc[mt][nt][3]);
            }
        }
    }
#undef LDG_CHUNK
#undef CVT_STS
#undef COMPUTE
}

// ============================ per-pair epilogue (register-blocked) ============================
// shared layout (word offsets into sh[]):
//   FS   @ 0     (36x41 = 1476; region sized 1600, reused by M1 [40x40])
//   Am   @ 1600  (40x37 = 1480)   a[l][r] = exp(FS*rnl)
//   Cm   @ 3080  (36x41 = 1476)   c[r][l] = exp(FS*cnl)
//   M2   @ 4556  (36x40 = 1440)   C.H
//   Gs   @ 5996  (36x36 = 1296)
//   Hs   @ 7292  (40x40 = 1600)
__global__ void __launch_bounds__(128) pair_epilogue(const float* __restrict__ S,
                                                     float* __restrict__ out) {
    __shared__ __align__(16) float sh[8892];
    __shared__ float Pb[NR], Qi[NL], rnl[NR], cnl[NL], s1s[NL], s2s[NR];
    float* FS = sh;
    float* M1 = sh;            // aliases FS (FS dead before M1 written)
    float* Am = sh + 1600;
    float* Cm = sh + 3080;
    float* M2 = sh + 4556;
    float* Gs = sh + 5996;
    float* Hs = sh + 7292;
    const int i = blockIdx.x, b = blockIdx.y, tid = threadIdx.x;

    const float* Sp = S + (size_t)i * NL * MT + (size_t)b * NR;
    for (int idx = tid; idx < NR * NL; idx += 128) {
        int l = idx / NR, r = idx - l * NR;
        FS[r * 41 + l] = __ldcs(Sp + (size_t)l * MT + r);
    }
    for (int idx = tid; idx < NR * NR; idx += 128) Gs[idx] = g_G[(size_t)b * (NR * NR) + idx];
    for (int idx = tid; idx < NL * NL; idx += 128) Hs[idx] = g_H[(size_t)i * (NL * NL) + idx];
    if (tid < NR) Pb[tid] = g_P[(size_t)i * MT + b * NR + tid];
    else if (tid >= 64 && tid < 64 + NL) Qi[tid - 64] = g_Q[(size_t)b * NT + i * NL + (tid - 64)];
    __syncthreads();

    if (tid < NL) {                        // column norms over r -> lambda/cn
        int l = tid; float s = 0.f;
#pragma unroll
        for (int r = 0; r < NR; r++) { float v = FS[r * 41 + l]; s = fmaf(v, v, s); }
        cnl[l] = LAMS / (sqrtf(s) + EPSF);
    } else if (tid >= 64 && tid < 64 + NR) {  // row norms over l -> lambda/rn
        int r = tid - 64; float s = 0.f;
#pragma unroll
        for (int l = 0; l < NL; l++) { float v = FS[r * 41 + l]; s = fmaf(v, v, s); }
        rnl[r] = LAMS / (sqrtf(s) + EPSF);
    }
    __syncthreads();

    // exp matrices: both directions from the same FS element
    for (int idx = tid; idx < NR * NL; idx += 128) {
        int r = idx / NL, l = idx - r * NL;
        float v = FS[r * 41 + l];
        Am[l * 37 + r] = __expf(v * rnl[r]);
        Cm[r * 41 + l] = __expf(v * cnl[l]);
    }
    __syncthreads();   // FS fully consumed; M1 may now overwrite it

    // register-blocked mini-GEMMs: 180 4x4 tasks (90 for M1, 90 for M2)
    for (int task = tid; task < 180; task += 128) {
        float a00 = 0.f, a01 = 0.f, a02 = 0.f, a03 = 0.f;
        float a10 = 0.f, a11 = 0.f, a12 = 0.f, a13 = 0.f;
        float a20 = 0.f, a21 = 0.f, a22 = 0.f, a23 = 0.f;
        float a30 = 0.f, a31 = 0.f, a32 = 0.f, a33 = 0.f;
        if (task < 90) {
            // M1[l][r] = sum_r' Am[l][r'] G[r'][r]; tile 4l x 4r
            int lg = task / 9, rg = task - lg * 9;
            const float* Ab = Am + lg * 4 * 37;
#pragma unroll 4
            for (int rp = 0; rp < NR; rp++) {
                float s0 = Ab[rp], s1 = Ab[37 + rp], s2 = Ab[74 + rp], s3 = Ab[111 + rp];
                float4 gv = *(const float4*)(Gs + rp * NR + rg * 4);
                a00 = fmaf(s0, gv.x, a00); a01 = fmaf(s0, gv.y, a01);
                a02 = fmaf(s0, gv.z, a02); a03 = fmaf(s0, gv.w, a03);
                a10 = fmaf(s1, gv.x, a10); a11 = fmaf(s1, gv.y, a11);
                a12 = fmaf(s1, gv.z, a12); a13 = fmaf(s1, gv.w, a13);
                a20 = fmaf(s2, gv.x, a20); a21 = fmaf(s2, gv.y, a21);
                a22 = fmaf(s2, gv.z, a22); a23 = fmaf(s2, gv.w, a23);
                a30 = fmaf(s3, gv.x, a30); a31 = fmaf(s3, gv.y, a31);
                a32 = fmaf(s3, gv.z, a32); a33 = fmaf(s3, gv.w, a33);
            }
            float* d = M1 + lg * 4 * 40 + rg * 4;
            *(float4*)(d)        = make_float4(a00, a01, a02, a03);
            *(float4*)(d + 40)   = make_float4(a10, a11, a12, a13);
            *(float4*)(d + 80)   = make_float4(a20, a21, a22, a23);
            *(float4*)(d + 120)  = make_float4(a30, a31, a32, a33);
        } else {
            // M2[r][l] = sum_l' Cm[r][l'] H[l'][l]; tile 4r x 4l
            int t2 = task - 90;
            int rg = t2 / 10, lg = t2 - rg * 10;
            const float* Cb = Cm + rg * 4 * 41;
#pragma unroll 4
            for (int lp = 0; lp < NL; lp++) {
                float s0 = Cb[lp], s1 = Cb[41 + lp], s2 = Cb[82 + lp], s3 = Cb[123 + lp];
                float4 hv = *(const float4*)(Hs + lp * NL + lg * 4);
                a00 = fmaf(s0, hv.x, a00); a01 = fmaf(s0, hv.y, a01);
                a02 = fmaf(s0, hv.z, a02); a03 = fmaf(s0, hv.w, a03);
                a10 = fmaf(s1, hv.x, a10); a11 = fmaf(s1, hv.y, a11);
                a12 = fmaf(s1, hv.z, a12); a13 = fmaf(s1, hv.w, a13);
                a20 = fmaf(s2, hv.x, a20); a21 = fmaf(s2, hv.y, a21);
                a22 = fmaf(s2, hv.z, a22); a23 = fmaf(s2, hv.w, a23);
                a30 = fmaf(s3, hv.x, a30); a31 = fmaf(s3, hv.y, a31);
                a32 = fmaf(s3, hv.z, a32); a33 = fmaf(s3, hv.w, a33);
            }
            float* d = M2 + rg * 4 * 40 + lg * 4;
            *(float4*)(d)        = make_float4(a00, a01, a02, a03);
            *(float4*)(d + 40)   = make_float4(a10, a11, a12, a13);
            *(float4*)(d + 80)   = make_float4(a20, a21, a22, a23);
            *(float4*)(d + 120)  = make_float4(a30, a31, a32, a33);
        }
    }
    __syncthreads();

    if (tid < NL) {                        // t2i: word l (softmax norm cancels)
        int l = tid; float w12 = 0.f, w2 = 0.f;
#pragma unroll
        for (int r = 0; r < NR; r++) {
            float a = Am[l * 37 + r];
            w12 = fmaf(a, Pb[r], w12);
            w2 = fmaf(a, M1[l * 40 + r], w2);
        }
        float den = fmaxf(g_w1t[i] * sqrtf(fmaxf(w2, 0.f)), EPSF);
        s1s[l] = __fdividef(w12, den);
    } else if (tid >= 64 && tid < 64 + NR) {   // i2t: region r
        int r = tid - 64; float w12 = 0.f, w2 = 0.f;
#pragma unroll
        for (int l = 0; l < NL; l++) {
            float cc = Cm[r * 41 + l];
            w12 = fmaf(cc, Qi[l], w12);
            w2 = fmaf(cc, M2[r * 40 + l], w2);
        }
        float den = fmaxf(g_w1i[b] * sqrtf(fmaxf(w2, 0.f)), EPSF);
        s2s[r] = __fdividef(w12, den);
    }
    __syncthreads();

    if (tid == 0) {
        float m1 = 0.f, m2 = 0.f;
#pragma unroll
        for (int l = 0; l < NL; l++) m1 += s1s[l];
#pragma unroll
        for (int r = 0; r < NR; r++) m2 += s2s[r];
        out[(size_t)b * NB + i] = g_base[b * NB + i] + m1 * (1.f / NL) + m2 * (1.f / NR);
    }
}

// ============================ launch ============================
extern "C" void kernel_launch(void* const* d_in, const int* in_sizes, int n_in,
                              void* d_out, int out_size) {
    (void)in_sizes; (void)n_in; (void)out_size;
    const float* pool_img = (const float*)d_in[0];
    const float* img_emb  = (const float*)d_in[1];
    const float* pool_txt = (const float*)d_in[2];
    const float* cap_emb  = (const float*)d_in[3];
    float* out = (float*)d_out;

    cudaFuncSetAttribute((const void*)gram_kernel,
                         cudaFuncAttributeMaxDynamicSharedMemorySize, NL * ND * 4);
    cudaFuncSetAttribute((const void*)s_gemm,
                         cudaFuncAttributeMaxDynamicSharedMemorySize, GEMM_SMEM);

    float* dS = nullptr;
    cudaGetSymbolAddress((void**)&dS, g_S);

    // order: s_gemm at launch index 3 (profiled slot)
    norm_kernel<<<64, 256>>>(pool_img, pool_txt);
    gram_kernel<<<NB, 256, NR * ND * 4>>>(img_emb, NR, 0);
    gram_kernel<<<NB, 256, NL * ND * 4>>>(cap_emb, NL, 1);
    s_gemm<<<dim3(41, 74), 256, GEMM_SMEM>>>(img_emb, cap_emb, pool_img, pool_txt, dS);
    sgemm_tn<<<dim3(NB / 64, NB / 64), 256>>>(pool_img, pool_txt, NB, NB, ND);
    pair_epilogue<<<dim3(NB, NB), 128>>>(dS, out);
}

// round 6
// speedup vs baseline: 5.7635x; 1.0859x over previous
#include <cuda_runtime.h>
#include <cuda_bf16.h>
#include <math.h>
#include <cstdint>

#define NB 256
#define NR 36
#define NL 40
#define ND 1024
#define MT (NB * NR)   /* 9216  */
#define NT (NB * NL)   /* 10240 */
#define EPSF 1e-8f
#define LAMS 9.0f

// ---- scratch (device globals; no allocation allowed) ----
__device__ float g_S[(size_t)MT * NT];   // S^T[n][m], leaky-relu'd raw dots (378MB)
__device__ float g_P[NB * NB * NR];      // P[i][b*36+r] = img_emb[b,r] . pool_txt[i]
__device__ float g_Q[NB * NB * NL];      // Q[b][i*40+l] = cap_emb[i,l] . pool_img[b]
__device__ float g_G[NB * NR * NR];      // per-image region Gram
__device__ float g_H[NB * NL * NL];      // per-caption word Gram
__device__ float g_base[NB * NB];        // pool_img @ pool_txt^T
__device__ float g_w1i[NB];
__device__ float g_w1t[NB];

__device__ __forceinline__ float4 ldg4(const float* p) {
    return *reinterpret_cast<const float4*>(p);
}
__device__ __forceinline__ uint32_t pack_bf2(float x, float y) {
    __nv_bfloat162 h = __float22bfloat162_rn(make_float2(x, y));
    return *reinterpret_cast<uint32_t*>(&h);
}
__device__ __forceinline__ void mma_bf16(float* c, const uint32_t* a, const uint32_t* b) {
    asm volatile(
        "mma.sync.aligned.m16n8k16.row.col.f32.bf16.bf16.f32 "
        "{%0,%1,%2,%3}, {%4,%5,%6,%7}, {%8,%9}, {%0,%1,%2,%3};"
        : "+f"(c[0]), "+f"(c[1]), "+f"(c[2]), "+f"(c[3])
        : "r"(a[0]), "r"(a[1]), "r"(a[2]), "r"(a[3]), "r"(b[0]), "r"(b[1]));
}

// ============================ precompute kernels ============================
__global__ void norm_kernel(const float* __restrict__ pi, const float* __restrict__ pt) {
    int w = blockIdx.x * 8 + (threadIdx.x >> 5);
    int lane = threadIdx.x & 31;
    const float* src = (w < NB) ? (pi + (size_t)w * ND) : (pt + (size_t)(w - NB) * ND);
    float s = 0.f;
    for (int j = lane; j < ND; j += 32) { float v = src[j]; s = fmaf(v, v, s); }
#pragma unroll
    for (int o = 16; o; o >>= 1) s += __shfl_down_sync(0xffffffffu, s, o);
    if (lane == 0) {
        float r = sqrtf(s);
        if (w < NB) g_w1i[w] = r; else g_w1t[w - NB] = r;
    }
}

// fp32 base gemm (pool_img @ pool_txt^T)
__global__ void sgemm_tn(const float* __restrict__ A, const float* __restrict__ Bm,
                         int M, int N, int K) {
    float* C = g_base;
    __shared__ float As[16 * 64];
    __shared__ float Bs[16 * 64];
    int tid = threadIdx.x;
    int tx = tid & 15, ty = tid >> 4;
    int m0 = blockIdx.y * 64, n0 = blockIdx.x * 64;
    int row = tid >> 2, q = tid & 3;
    float acc[4][4] = {};
    for (int k0 = 0; k0 < K; k0 += 16) {
        float4 a = ldg4(A + (size_t)(m0 + row) * K + k0 + q * 4);
        float4 bb = ldg4(Bm + (size_t)(n0 + row) * K + k0 + q * 4);
        As[(q * 4 + 0) * 64 + row] = a.x;  As[(q * 4 + 1) * 64 + row] = a.y;
        As[(q * 4 + 2) * 64 + row] = a.z;  As[(q * 4 + 3) * 64 + row] = a.w;
        Bs[(q * 4 + 0) * 64 + row] = bb.x; Bs[(q * 4 + 1) * 64 + row] = bb.y;
        Bs[(q * 4 + 2) * 64 + row] = bb.z; Bs[(q * 4 + 3) * 64 + row] = bb.w;
        __syncthreads();
#pragma unroll
        for (int k = 0; k < 16; k++) {
            float4 av = *(const float4*)(As + k * 64 + ty * 4);
            float4 bv = *(const float4*)(Bs + k * 64 + tx * 4);
            float aa[4] = {av.x, av.y, av.z, av.w};
            float bw[4] = {bv.x, bv.y, bv.z, bv.w};
#pragma unroll
            for (int ii = 0; ii < 4; ii++)
#pragma unroll
                for (int jj = 0; jj < 4; jj++)
                    acc[ii][jj] = fmaf(aa[ii], bw[jj], acc[ii][jj]);
        }
        __syncthreads();
    }
#pragma unroll
    for (int ii = 0; ii < 4; ii++)
#pragma unroll
        for (int jj = 0; jj < 4; jj++)
            C[(size_t)(m0 + ty * 4 + ii) * N + n0 + tx * 4 + jj] = acc[ii][jj];
}

// ---- per-row Gram, 4x4 register-blocked, symmetric (tr<=tc computed, mirrored) ----
__global__ void gram_kernel(const float* __restrict__ emb, int ROWS, int which) {
    extern __shared__ float Es[];
    float* out = which ? g_H : g_G;
    int b = blockIdx.x, tid = threadIdx.x;
    int wid = tid >> 5, lane = tid & 31;
    int n = ROWS * ND;
    int np = ROWS * ROWS;
    for (int idx = tid; idx < n; idx += 256) Es[idx] = emb[(size_t)b * n + idx];
    __syncthreads();
    int nt4 = ROWS / 4;
    int count = nt4 * (nt4 + 1) / 2;
    for (int p = wid; p < count; p += 8) {
        int pl = p, tr = 0;
        while (pl >= nt4 - tr) { pl -= nt4 - tr; tr++; }
        int tc = tr + pl;
        const float* E1 = Es + (size_t)tr * 4 * ND;
        const float* E2 = Es + (size_t)tc * 4 * ND;
        float acc[4][4] = {};
        for (int kk = 0; kk < ND; kk += 32) {
            int k = kk + lane;
            float e1[4], e2[4];
#pragma unroll
            for (int j = 0; j < 4; j++) { e1[j] = E1[j * ND + k]; e2[j] = E2[j * ND + k]; }
#pragma unroll
            for (int j = 0; j < 4; j++)
#pragma unroll
                for (int jj = 0; jj < 4; jj++)
                    acc[j][jj] = fmaf(e1[j], e2[jj], acc[j][jj]);
        }
#pragma unroll
        for (int j = 0; j < 4; j++)
#pragma unroll
            for (int jj = 0; jj < 4; jj++) {
#pragma unroll
                for (int o = 16; o; o >>= 1)
                    acc[j][jj] += __shfl_xor_sync(0xffffffffu, acc[j][jj], o);
            }
        if (lane == 0) {
#pragma unroll
            for (int j = 0; j < 4; j++)
#pragma unroll
                for (int jj = 0; jj < 4; jj++) {
                    float v = acc[j][jj];
                    out[(size_t)b * np + (tr * 4 + j) * ROWS + tc * 4 + jj] = v;
                    out[(size_t)b * np + (tc * 4 + jj) * ROWS + tr * 4 + j] = v;
                }
        }
    }
}

// ============================ bf16 mma.sync folded GEMM ============================
#define BM 128
#define BN 256
#define BK 32
#define ASZW (BM * 20)
#define BSZW (BN * 20)
#define STAGEW (ASZW + BSZW)
#define GEMM_SMEM (2 * STAGEW * 4)

__global__ void __launch_bounds__(256, 1) s_gemm(const float* __restrict__ img,
                                                 const float* __restrict__ cap,
                                                 const float* __restrict__ pimg,
                                                 const float* __restrict__ ptxt,
                                                 float* __restrict__ S) {
    extern __shared__ uint32_t smw[];
    const int tid = threadIdx.x;
    const int wid = tid >> 5;
    const int lane = tid & 31;
    const int g = lane >> 2;
    const int t = lane & 3;
    const int wm = wid >> 2;
    const int wn = wid & 3;
    const int by = blockIdx.y;
    const int bx = blockIdx.x;
    const int m0 = by * BM;
    const int n0 = bx * BN;
    const bool pBlk = (bx == 40);
    const bool qBlk = (by >= 72);

    const float* Ag = qBlk ? (pimg + (size_t)(by - 72) * BM * ND)
                           : (img + (size_t)m0 * ND);
    const float* Bg = pBlk ? ptxt : (cap + (size_t)n0 * ND);

    const int row0 = tid >> 3;
    const int qq = tid & 7;

    float cacc[4][8][4];
#pragma unroll
    for (int a = 0; a < 4; a++)
#pragma unroll
        for (int bb = 0; bb < 8; bb++)
#pragma unroll
            for (int cc = 0; cc < 4; cc++) cacc[a][bb][cc] = 0.f;

    float4 ra[4], rb[8];

#define LDG_CHUNK(kc) do {                                                     \
    _Pragma("unroll")                                                          \
    for (int j = 0; j < 4; j++)                                                \
        ra[j] = ldg4(Ag + (size_t)(row0 + j * 32) * ND + (kc) + qq * 4);       \
    _Pragma("unroll")                                                          \
    for (int j = 0; j < 8; j++)                                                \
        rb[j] = ldg4(Bg + (size_t)(row0 + j * 32) * ND + (kc) + qq * 4);       \
} while (0)

#define CVT_STS(stg) do {                                                      \
    uint32_t* Ad = smw + (stg) * STAGEW;                                       \
    uint32_t* Bd = Ad + ASZW;                                                  \
    _Pragma("unroll")                                                          \
    for (int j = 0; j < 4; j++) {                                              \
        uint2* dst = (uint2*)(Ad + (row0 + j * 32) * 20 + qq * 2);             \
        *dst = make_uint2(pack_bf2(ra[j].x, ra[j].y), pack_bf2(ra[j].z, ra[j].w)); \
    }                                                                          \
    _Pragma("unroll")                                                          \
    for (int j = 0; j < 8; j++) {                                              \
        uint2* dst = (uint2*)(Bd + (row0 + j * 32) * 20 + qq * 2);             \
        *dst = make_uint2(pack_bf2(rb[j].x, rb[j].y), pack_bf2(rb[j].z, rb[j].w)); \
    }                                                                          \
} while (0)

#define COMPUTE(stg, ks) do {                                                  \
    const uint32_t* Aw = smw + (stg) * STAGEW;                                 \
    const uint32_t* Bw = Aw + ASZW;                                            \
    const int kw = (ks) * 8 + t;                                               \
    uint32_t af[4][4];                                                         \
    uint32_t bf[8][2];                                                         \
    _Pragma("unroll")                                                          \
    for (int mt = 0; mt < 4; mt++) {                                           \
        int r0 = (wm * 64 + mt * 16 + g) * 20;                                 \
        af[mt][0] = Aw[r0 + kw];                                               \
        af[mt][1] = Aw[r0 + 160 + kw];                                         \
        af[mt][2] = Aw[r0 + kw + 4];                                           \
        af[mt][3] = Aw[r0 + 160 + kw + 4];                                     \
    }                                                                          \
    _Pragma("unroll")                                                          \
    for (int nt = 0; nt < 8; nt++) {                                           \
        int c0 = (wn * 64 + nt * 8 + g) * 20;                                  \
        bf[nt][0] = Bw[c0 + kw];                                               \
        bf[nt][1] = Bw[c0 + kw + 4];                                           \
    }                                                                          \
    _Pragma("unroll")                                                          \
    for (int mt = 0; mt < 4; mt++)                                             \
        _Pragma("unroll")                                                      \
        for (int nt = 0; nt < 8; nt++)                                         \
            mma_bf16(cacc[mt][nt], af[mt], bf[nt]);                            \
} while (0)

    LDG_CHUNK(0);
    CVT_STS(0);
    __syncthreads();

    int st = 0;
#pragma unroll 1
    for (int c = 0; c < 32; c++) {
        int nst = st ^ 1;
        bool more = (c < 31);
        if (more) LDG_CHUNK((c + 1) * BK);
        COMPUTE(st, 0);
        COMPUTE(st, 1);
        if (more) CVT_STS(nst);
        __syncthreads();
        st = nst;
    }

    if (pBlk && qBlk) return;

    if (!pBlk && !qBlk) {
#pragma unroll
        for (int mt = 0; mt < 4; mt++) {
            int m = m0 + wm * 64 + mt * 16 + g;
#pragma unroll
            for (int nt = 0; nt < 8; nt++) {
                int n = n0 + wn * 64 + nt * 8 + 2 * t;
                float v0 = cacc[mt][nt][0]; v0 = (v0 >= 0.f) ? v0 : 0.1f * v0;
                float v1 = cacc[mt][nt][1]; v1 = (v1 >= 0.f) ? v1 : 0.1f * v1;
                float v2 = cacc[mt][nt][2]; v2 = (v2 >= 0.f) ? v2 : 0.1f * v2;
                float v3 = cacc[mt][nt][3]; v3 = (v3 >= 0.f) ? v3 : 0.1f * v3;
                __stcs(S + (size_t)n * MT + m, v0);
                __stcs(S + (size_t)(n + 1) * MT + m, v1);
                __stcs(S + (size_t)n * MT + m + 8, v2);
                __stcs(S + (size_t)(n + 1) * MT + m + 8, v3);
            }
        }
    } else if (pBlk) {
#pragma unroll
        for (int mt = 0; mt < 4; mt++) {
            int m = m0 + wm * 64 + mt * 16 + g;
#pragma unroll
            for (int nt = 0; nt < 8; nt++) {
                int i = wn * 64 + nt * 8 + 2 * t;
                __stcs(g_P + (size_t)i * MT + m, cacc[mt][nt][0]);
                __stcs(g_P + (size_t)(i + 1) * MT + m, cacc[mt][nt][1]);
                __stcs(g_P + (size_t)i * MT + m + 8, cacc[mt][nt][2]);
                __stcs(g_P + (size_t)(i + 1) * MT + m + 8, cacc[mt][nt][3]);
            }
        }
    } else {
#pragma unroll
        for (int mt = 0; mt < 4; mt++) {
            int b = (by - 72) * BM + wm * 64 + mt * 16 + g;
#pragma unroll
            for (int nt = 0; nt < 8; nt++) {
                int n = n0 + wn * 64 + nt * 8 + 2 * t;
                __stcs(g_Q + (size_t)b * NT + n, cacc[mt][nt][0]);
                __stcs(g_Q + (size_t)b * NT + n + 1, cacc[mt][nt][1]);
                __stcs(g_Q + (size_t)(b + 8) * NT + n, cacc[mt][nt][2]);
                __stcs(g_Q + (size_t)(b + 8) * NT + n + 1, cacc[mt][nt][3]);
            }
        }
    }
#undef LDG_CHUNK
#undef CVT_STS
#undef COMPUTE
}

// ============================ per-pair epilogue: 2 pairs/block, vectorized ============================
// dynamic smem layout (floats). Per half h (size 7984):
//   FS @ 0     stride 41 (36 r x 40 l), aliased by M1 (40x40 stride 40)
//   Am @ 1600  stride 44 (40 l rows)
//   Cm @ 3360  stride 44 (36 r rows)
//   M2 @ 4944  stride 40 (36 r rows)
//   Hs @ 6384  stride 40 (40 rows)
// Gs @ 15968 (36x36)
#define HSZ 7984
#define EPI_SMEM ((2 * HSZ + 1296) * 4)

__global__ void __launch_bounds__(256) pair_epilogue(const float* __restrict__ S,
                                                     float* __restrict__ out) {
    extern __shared__ float sh[];
    __shared__ float Pb[2][NR], Qi[2][NL], rnl[2][NR], cnl[2][NL], s1s[2][NL], s2s[2][NR];
    const int tid = threadIdx.x;
    const int h = tid >> 7;
    const int tt = tid & 127;
    const int i = blockIdx.x * 2 + h;
    const int b = blockIdx.y;

    float* hb = sh + h * HSZ;
    float* FS = hb;
    float* M1 = hb;            // aliases FS (dead before M1 written)
    float* Am = hb + 1600;
    float* Cm = hb + 3360;
    float* M2 = hb + 4944;
    float* Hs = hb + 6384;
    float* Gs = sh + 2 * HSZ;

    const float* Sp = S + (size_t)i * NL * MT + (size_t)b * NR;
    for (int idx = tt; idx < NR * NL; idx += 128) {
        int l = idx / NR, r = idx - l * NR;
        FS[r * 41 + l] = __ldcs(Sp + (size_t)l * MT + r);
    }
    for (int idx = tid; idx < NR * NR; idx += 256) Gs[idx] = g_G[(size_t)b * (NR * NR) + idx];
    for (int idx = tt; idx < NL * NL; idx += 128) Hs[idx] = g_H[(size_t)i * (NL * NL) + idx];
    if (tt < NR) Pb[h][tt] = g_P[(size_t)i * MT + b * NR + tt];
    else if (tt >= 64 && tt < 64 + NL) Qi[h][tt - 64] = g_Q[(size_t)b * NT + i * NL + (tt - 64)];
    __syncthreads();

    if (tt < NL) {                         // column norms over r -> lambda/cn
        int l = tt; float s = 0.f;
#pragma unroll
        for (int r = 0; r < NR; r++) { float v = FS[r * 41 + l]; s = fmaf(v, v, s); }
        cnl[h][l] = LAMS / (sqrtf(s) + EPSF);
    } else if (tt >= 64 && tt < 64 + NR) { // row norms over l -> lambda/rn
        int r = tt - 64; float s = 0.f;
#pragma unroll
        for (int l = 0; l < NL; l++) { float v = FS[r * 41 + l]; s = fmaf(v, v, s); }
        rnl[h][r] = LAMS / (sqrtf(s) + EPSF);
    }
    __syncthreads();

    // exp matrices
    for (int idx = tt; idx < NR * NL; idx += 128) {
        int l = idx / NR, r = idx - l * NR;
        float v = FS[r * 41 + l];
        Am[l * 44 + r] = __expf(v * rnl[h][r]);
        Cm[r * 44 + l] = __expf(v * cnl[h][l]);
    }
    __syncthreads();   // FS fully consumed; M1 may alias

    // vectorized register-blocked mini-GEMMs: 180 tasks per half
    for (int task = tt; task < 180; task += 128) {
        float4 acc0 = make_float4(0.f, 0.f, 0.f, 0.f);
        float4 acc1 = acc0, acc2 = acc0, acc3 = acc0;
        if (task < 90) {
            // M1[l][r] = sum_r' Am[l][r'] G[r'][r]; tile 4l x 4r
            int lg = task / 9, rg = task - lg * 9;
            const float* Ab = Am + lg * 4 * 44;
            const float* Gb = Gs + rg * 4;
#pragma unroll
            for (int rp4 = 0; rp4 < 9; rp4++) {
                float4 a0 = *(const float4*)(Ab + rp4 * 4);
                float4 a1 = *(const float4*)(Ab + 44 + rp4 * 4);
                float4 a2 = *(const float4*)(Ab + 88 + rp4 * 4);
                float4 a3 = *(const float4*)(Ab + 132 + rp4 * 4);
                float4 g0 = *(const float4*)(Gb + (rp4 * 4 + 0) * 36);
                float4 g1 = *(const float4*)(Gb + (rp4 * 4 + 1) * 36);
                float4 g2 = *(const float4*)(Gb + (rp4 * 4 + 2) * 36);
                float4 g3 = *(const float4*)(Gb + (rp4 * 4 + 3) * 36);
#define ACC4(ACC, AV)                                                          \
                ACC.x = fmaf(AV.x, g0.x, ACC.x); ACC.y = fmaf(AV.x, g0.y, ACC.y); \
                ACC.z = fmaf(AV.x, g0.z, ACC.z); ACC.w = fmaf(AV.x, g0.w, ACC.w); \
                ACC.x = fmaf(AV.y, g1.x, ACC.x); ACC.y = fmaf(AV.y, g1.y, ACC.y); \
                ACC.z = fmaf(AV.y, g1.z, ACC.z); ACC.w = fmaf(AV.y, g1.w, ACC.w); \
                ACC.x = fmaf(AV.z, g2.x, ACC.x); ACC.y = fmaf(AV.z, g2.y, ACC.y); \
                ACC.z = fmaf(AV.z, g2.z, ACC.z); ACC.w = fmaf(AV.z, g2.w, ACC.w); \
                ACC.x = fmaf(AV.w, g3.x, ACC.x); ACC.y = fmaf(AV.w, g3.y, ACC.y); \
                ACC.z = fmaf(AV.w, g3.z, ACC.z); ACC.w = fmaf(AV.w, g3.w, ACC.w);
                ACC4(acc0, a0) ACC4(acc1, a1) ACC4(acc2, a2) ACC4(acc3, a3)
            }
            float* d = M1 + lg * 4 * 40 + rg * 4;
            *(float4*)(d)       = acc0;
            *(float4*)(d + 40)  = acc1;
            *(float4*)(d + 80)  = acc2;
            *(float4*)(d + 120) = acc3;
        } else {
            // M2[r][l] = sum_l' Cm[r][l'] H[l'][l]; tile 4r x 4l
            int t2 = task - 90;
            int rg = t2 / 10, lg = t2 - rg * 10;
            const float* Cb = Cm + rg * 4 * 44;
            const float* Hb = Hs + lg * 4;
#pragma unroll
            for (int lp4 = 0; lp4 < 10; lp4++) {
                float4 a0 = *(const float4*)(Cb + lp4 * 4);
                float4 a1 = *(const float4*)(Cb + 44 + lp4 * 4);
                float4 a2 = *(const float4*)(Cb + 88 + lp4 * 4);
                float4 a3 = *(const float4*)(Cb + 132 + lp4 * 4);
                float4 g0 = *(const float4*)(Hb + (lp4 * 4 + 0) * 40);
                float4 g1 = *(const float4*)(Hb + (lp4 * 4 + 1) * 40);
                float4 g2 = *(const float4*)(Hb + (lp4 * 4 + 2) * 40);
                float4 g3 = *(const float4*)(Hb + (lp4 * 4 + 3) * 40);
                ACC4(acc0, a0) ACC4(acc1, a1) ACC4(acc2, a2) ACC4(acc3, a3)
#undef ACC4
            }
            float* d = M2 + rg * 4 * 40 + lg * 4;
            *(float4*)(d)       = acc0;
            *(float4*)(d + 40)  = acc1;
            *(float4*)(d + 80)  = acc2;
            *(float4*)(d + 120) = acc3;
        }
    }
    __syncthreads();

    if (tt < NL) {                         // t2i: word l
        int l = tt; float w12 = 0.f, w2 = 0.f;
#pragma unroll
        for (int r = 0; r < NR; r++) {
            float a = Am[l * 44 + r];
            w12 = fmaf(a, Pb[h][r], w12);
            w2 = fmaf(a, M1[l * 40 + r], w2);
        }
        float den = fmaxf(g_w1t[i] * sqrtf(fmaxf(w2, 0.f)), EPSF);
        s1s[h][l] = __fdividef(w12, den);
    } else if (tt >= 64 && tt < 64 + NR) { // i2t: region r
        int r = tt - 64; float w12 = 0.f, w2 = 0.f;
#pragma unroll
        for (int l = 0; l < NL; l++) {
            float cc = Cm[r * 44 + l];
            w12 = fmaf(cc, Qi[h][l], w12);
            w2 = fmaf(cc, M2[r * 40 + l], w2);
        }
        float den = fmaxf(g_w1i[b] * sqrtf(fmaxf(w2, 0.f)), EPSF);
        s2s[h][r] = __fdividef(w12, den);
    }
    __syncthreads();

    if (tt == 0) {
        float m1 = 0.f, m2 = 0.f;
#pragma unroll
        for (int l = 0; l < NL; l++) m1 += s1s[h][l];
#pragma unroll
        for (int r = 0; r < NR; r++) m2 += s2s[h][r];
        out[(size_t)b * NB + i] = g_base[b * NB + i] + m1 * (1.f / NL) + m2 * (1.f / NR);
    }
}

// ============================ launch ============================
extern "C" void kernel_launch(void* const* d_in, const int* in_sizes, int n_in,
                              void* d_out, int out_size) {
    (void)in_sizes; (void)n_in; (void)out_size;
    const float* pool_img = (const float*)d_in[0];
    const float* img_emb  = (const float*)d_in[1];
    const float* pool_txt = (const float*)d_in[2];
    const float* cap_emb  = (const float*)d_in[3];
    float* out = (float*)d_out;

    cudaFuncSetAttribute((const void*)gram_kernel,
                         cudaFuncAttributeMaxDynamicSharedMemorySize, NL * ND * 4);
    cudaFuncSetAttribute((const void*)s_gemm,
                         cudaFuncAttributeMaxDynamicSharedMemorySize, GEMM_SMEM);
    cudaFuncSetAttribute((const void*)pair_epilogue,
                         cudaFuncAttributeMaxDynamicSharedMemorySize, EPI_SMEM);

    float* dS = nullptr;
    cudaGetSymbolAddress((void**)&dS, g_S);

    // order: s_gemm at launch index 3 (profiled slot)
    norm_kernel<<<64, 256>>>(pool_img, pool_txt);
    gram_kernel<<<NB, 256, NR * ND * 4>>>(img_emb, NR, 0);
    gram_kernel<<<NB, 256, NL * ND * 4>>>(cap_emb, NL, 1);
    s_gemm<<<dim3(41, 74), 256, GEMM_SMEM>>>(img_emb, cap_emb, pool_img, pool_txt, dS);
    sgemm_tn<<<dim3(NB / 64, NB / 64), 256>>>(pool_img, pool_txt, NB, NB, ND);
    pair_epilogue<<<dim3(NB / 2, NB), 256, EPI_SMEM>>>(dS, out);
}

// round 7
// speedup vs baseline: 6.1935x; 1.0746x over previous
#include <cuda_runtime.h>
#include <cuda_bf16.h>
#include <math.h>
#include <cstdint>

#define NB 256
#define NR 36
#define NL 40
#define ND 1024
#define MT (NB * NR)   /* 9216  */
#define NT (NB * NL)   /* 10240 */
#define EPSF 1e-8f
#define LAMS 9.0f

#define MROWS 9472     /* 9216 img rows + 256 pool_img */
#define NROWS 10496    /* 10240 cap rows + 256 pool_txt */

// ---- scratch (device globals; no allocation allowed) ----
__device__ float g_S[(size_t)MT * NT];           // S^T[n][m], leaky-relu'd (378MB)
__device__ __nv_bfloat16 g_Ah[(size_t)MROWS * ND];  // bf16 img_emb ++ pool_img
__device__ __nv_bfloat16 g_Bh[(size_t)NROWS * ND];  // bf16 cap_emb ++ pool_txt
__device__ float g_P[NB * NB * NR];
__device__ float g_Q[NB * NB * NL];
__device__ float g_G[NB * NR * NR];
__device__ float g_H[NB * NL * NL];
__device__ float g_base[NB * NB];
__device__ float g_w1i[NB];
__device__ float g_w1t[NB];

__device__ __forceinline__ float4 ldg4(const float* p) {
    return *reinterpret_cast<const float4*>(p);
}
__device__ __forceinline__ uint32_t pack_bf2(float x, float y) {
    __nv_bfloat162 h = __float22bfloat162_rn(make_float2(x, y));
    return *reinterpret_cast<uint32_t*>(&h);
}
__device__ __forceinline__ void mma_bf16(float* c, const uint32_t* a, const uint32_t* b) {
    asm volatile(
        "mma.sync.aligned.m16n8k16.row.col.f32.bf16.bf16.f32 "
        "{%0,%1,%2,%3}, {%4,%5,%6,%7}, {%8,%9}, {%0,%1,%2,%3};"
        : "+f"(c[0]), "+f"(c[1]), "+f"(c[2]), "+f"(c[3])
        : "r"(a[0]), "r"(a[1]), "r"(a[2]), "r"(a[3]), "r"(b[0]), "r"(b[1]));
}
__device__ __forceinline__ void cpa16(uint32_t saddr, const void* gaddr) {
    asm volatile("cp.async.ca.shared.global [%0], [%1], 16;"
                 :: "r"(saddr), "l"(gaddr) : "memory");
}

// ============================ bf16 conversion (augmented operands) ============================
__global__ void cvt_kernel(const float* __restrict__ img, const float* __restrict__ pimg,
                           const float* __restrict__ cap, const float* __restrict__ ptxt) {
    size_t g8 = (size_t)blockIdx.x * 256 + threadIdx.x;   // one thread per 8 elements
    const size_t A8 = (size_t)MROWS * (ND / 8);           // 1,212,416
    const float* src;
    uint32_t* dst;
    if (g8 < A8) {
        size_t off = g8 * 8;
        size_t row = off >> 10, col = off & 1023;
        src = (row < 9216) ? (img + row * ND + col) : (pimg + (row - 9216) * ND + col);
        dst = reinterpret_cast<uint32_t*>(g_Ah) + g8 * 4;
    } else {
        size_t h8 = g8 - A8;
        size_t off = h8 * 8;
        size_t row = off >> 10, col = off & 1023;
        src = (row < 10240) ? (cap + row * ND + col) : (ptxt + (row - 10240) * ND + col);
        dst = reinterpret_cast<uint32_t*>(g_Bh) + h8 * 4;
    }
    float4 x = ldg4(src), y = ldg4(src + 4);
    *reinterpret_cast<uint4*>(dst) =
        make_uint4(pack_bf2(x.x, x.y), pack_bf2(x.z, x.w),
                   pack_bf2(y.x, y.y), pack_bf2(y.z, y.w));
}

// ============================ precompute kernels ============================
__global__ void norm_kernel(const float* __restrict__ pi, const float* __restrict__ pt) {
    int w = blockIdx.x * 8 + (threadIdx.x >> 5);
    int lane = threadIdx.x & 31;
    const float* src = (w < NB) ? (pi + (size_t)w * ND) : (pt + (size_t)(w - NB) * ND);
    float s = 0.f;
    for (int j = lane; j < ND; j += 32) { float v = src[j]; s = fmaf(v, v, s); }
#pragma unroll
    for (int o = 16; o; o >>= 1) s += __shfl_down_sync(0xffffffffu, s, o);
    if (lane == 0) {
        float r = sqrtf(s);
        if (w < NB) g_w1i[w] = r; else g_w1t[w - NB] = r;
    }
}

__global__ void sgemm_tn(const float* __restrict__ A, const float* __restrict__ Bm,
                         int M, int N, int K) {
    float* C = g_base;
    __shared__ float As[16 * 64];
    __shared__ float Bs[16 * 64];
    int tid = threadIdx.x;
    int tx = tid & 15, ty = tid >> 4;
    int m0 = blockIdx.y * 64, n0 = blockIdx.x * 64;
    int row = tid >> 2, q = tid & 3;
    float acc[4][4] = {};
    for (int k0 = 0; k0 < K; k0 += 16) {
        float4 a = ldg4(A + (size_t)(m0 + row) * K + k0 + q * 4);
        float4 bb = ldg4(Bm + (size_t)(n0 + row) * K + k0 + q * 4);
        As[(q * 4 + 0) * 64 + row] = a.x;  As[(q * 4 + 1) * 64 + row] = a.y;
        As[(q * 4 + 2) * 64 + row] = a.z;  As[(q * 4 + 3) * 64 + row] = a.w;
        Bs[(q * 4 + 0) * 64 + row] = bb.x; Bs[(q * 4 + 1) * 64 + row] = bb.y;
        Bs[(q * 4 + 2) * 64 + row] = bb.z; Bs[(q * 4 + 3) * 64 + row] = bb.w;
        __syncthreads();
#pragma unroll
        for (int k = 0; k < 16; k++) {
            float4 av = *(const float4*)(As + k * 64 + ty * 4);
            float4 bv = *(const float4*)(Bs + k * 64 + tx * 4);
            float aa[4] = {av.x, av.y, av.z, av.w};
            float bw[4] = {bv.x, bv.y, bv.z, bv.w};
#pragma unroll
            for (int ii = 0; ii < 4; ii++)
#pragma unroll
                for (int jj = 0; jj < 4; jj++)
                    acc[ii][jj] = fmaf(aa[ii], bw[jj], acc[ii][jj]);
        }
        __syncthreads();
    }
#pragma unroll
    for (int ii = 0; ii < 4; ii++)
#pragma unroll
        for (int jj = 0; jj < 4; jj++)
            C[(size_t)(m0 + ty * 4 + ii) * N + n0 + tx * 4 + jj] = acc[ii][jj];
}

// per-row Gram, 4x4 register-blocked, symmetric
__global__ void gram_kernel(const float* __restrict__ emb, int ROWS, int which) {
    extern __shared__ float Es[];
    float* out = which ? g_H : g_G;
    int b = blockIdx.x, tid = threadIdx.x;
    int wid = tid >> 5, lane = tid & 31;
    int n = ROWS * ND;
    int np = ROWS * ROWS;
    for (int idx = tid; idx < n; idx += 256) Es[idx] = emb[(size_t)b * n + idx];
    __syncthreads();
    int nt4 = ROWS / 4;
    int count = nt4 * (nt4 + 1) / 2;
    for (int p = wid; p < count; p += 8) {
        int pl = p, tr = 0;
        while (pl >= nt4 - tr) { pl -= nt4 - tr; tr++; }
        int tc = tr + pl;
        const float* E1 = Es + (size_t)tr * 4 * ND;
        const float* E2 = Es + (size_t)tc * 4 * ND;
        float acc[4][4] = {};
        for (int kk = 0; kk < ND; kk += 32) {
            int k = kk + lane;
            float e1[4], e2[4];
#pragma unroll
            for (int j = 0; j < 4; j++) { e1[j] = E1[j * ND + k]; e2[j] = E2[j * ND + k]; }
#pragma unroll
            for (int j = 0; j < 4; j++)
#pragma unroll
                for (int jj = 0; jj < 4; jj++)
                    acc[j][jj] = fmaf(e1[j], e2[jj], acc[j][jj]);
        }
#pragma unroll
        for (int j = 0; j < 4; j++)
#pragma unroll
            for (int jj = 0; jj < 4; jj++) {
#pragma unroll
                for (int o = 16; o; o >>= 1)
                    acc[j][jj] += __shfl_xor_sync(0xffffffffu, acc[j][jj], o);
            }
        if (lane == 0) {
#pragma unroll
            for (int j = 0; j < 4; j++)
#pragma unroll
                for (int jj = 0; jj < 4; jj++) {
                    float v = acc[j][jj];
                    out[(size_t)b * np + (tr * 4 + j) * ROWS + tc * 4 + jj] = v;
                    out[(size_t)b * np + (tc * 4 + jj) * ROWS + tr * 4 + j] = v;
                }
        }
    }
}

// ============================ bf16 cp.async pipelined GEMM ============================
#define BM 128
#define BN 256
#define BK 32
#define ASZW (BM * 20)            /* 2560 words/stage for A */
#define STGW (ASZW + BN * 20)     /* 7680 words = 30720 B */
#define STAGES 4
#define GEMM_SMEM (STAGES * STGW * 4)   /* 122880 B */

__global__ void __launch_bounds__(256, 1) s_gemm(const __nv_bfloat16* __restrict__ Ah,
                                                 const __nv_bfloat16* __restrict__ Bh,
                                                 float* __restrict__ S) {
    extern __shared__ uint32_t smw[];
    uint32_t sb;
    asm("{ .reg .u64 t; cvta.to.shared.u64 t, %1; cvt.u32.u64 %0, t; }" : "=r"(sb) : "l"(smw));
    const int tid = threadIdx.x;
    const int wid = tid >> 5;
    const int lane = tid & 31;
    const int g = lane >> 2;
    const int t = lane & 3;
    const int wm = wid >> 2;
    const int wn = wid & 3;
    const int by = blockIdx.y;
    const int bx = blockIdx.x;
    const int m0 = by * BM;
    const int n0 = bx * BN;
    const bool pBlk = (bx == 40);
    const bool qBlk = (by >= 72);

    // cp.async lane geometry
    const int arow = tid >> 2;      // 0..63
    const int ac = tid & 3;         // 16B chunk within 64B row-slice
    const __nv_bfloat16* Agp = Ah + (size_t)(m0 + arow) * ND + ac * 8;
    const __nv_bfloat16* Bgp = Bh + (size_t)(n0 + arow) * ND + ac * 8;
    const uint32_t sA = sb + (uint32_t)(arow * 20 + ac * 4) * 4;
    const uint32_t sB = sb + (uint32_t)(ASZW + arow * 20 + ac * 4) * 4;

    float cacc[4][8][4];
#pragma unroll
    for (int a = 0; a < 4; a++)
#pragma unroll
        for (int bb = 0; bb < 8; bb++)
#pragma unroll
            for (int cc = 0; cc < 4; cc++) cacc[a][bb][cc] = 0.f;

#define ISSUE(stg, kc) do {                                                    \
    uint32_t so = (uint32_t)(stg) * (STGW * 4);                                \
    _Pragma("unroll")                                                          \
    for (int j = 0; j < 2; j++)                                                \
        cpa16(sA + so + j * (64 * 20 * 4), Agp + (size_t)j * 64 * ND + (kc));  \
    _Pragma("unroll")                                                          \
    for (int j = 0; j < 4; j++)                                                \
        cpa16(sB + so + j * (64 * 20 * 4), Bgp + (size_t)j * 64 * ND + (kc));  \
} while (0)

#define COMPUTE(stg, ks) do {                                                  \
    const uint32_t* Aw = smw + (stg) * STGW;                                   \
    const uint32_t* Bw = Aw + ASZW;                                            \
    const int kw = (ks) * 8 + t;                                               \
    uint32_t af[4][4];                                                         \
    uint32_t bf[8][2];                                                         \
    _Pragma("unroll")                                                          \
    for (int mt = 0; mt < 4; mt++) {                                           \
        int r0 = (wm * 64 + mt * 16 + g) * 20;                                 \
        af[mt][0] = Aw[r0 + kw];                                               \
        af[mt][1] = Aw[r0 + 160 + kw];                                         \
        af[mt][2] = Aw[r0 + kw + 4];                                           \
        af[mt][3] = Aw[r0 + 160 + kw + 4];                                     \
    }                                                                          \
    _Pragma("unroll")                                                          \
    for (int nt = 0; nt < 8; nt++) {                                           \
        int c0 = (wn * 64 + nt * 8 + g) * 20;                                  \
        bf[nt][0] = Bw[c0 + kw];                                               \
        bf[nt][1] = Bw[c0 + kw + 4];                                           \
    }                                                                          \
    _Pragma("unroll")                                                          \
    for (int mt = 0; mt < 4; mt++)                                             \
        _Pragma("unroll")                                                      \
        for (int nt = 0; nt < 8; nt++)                                         \
            mma_bf16(cacc[mt][nt], af[mt], bf[nt]);                            \
} while (0)

    // prologue: 3 stages in flight
    ISSUE(0, 0);  asm volatile("cp.async.commit_group;" ::: "memory");
    ISSUE(1, 32); asm volatile("cp.async.commit_group;" ::: "memory");
    ISSUE(2, 64); asm volatile("cp.async.commit_group;" ::: "memory");

#pragma unroll 1
    for (int c = 0; c < 32; c++) {
        asm volatile("cp.async.wait_group 2;" ::: "memory");
        __syncthreads();
        COMPUTE(c & 3, 0);
        COMPUTE(c & 3, 1);
        if (c < 29) ISSUE((c + 3) & 3, (c + 3) * BK);
        asm volatile("cp.async.commit_group;" ::: "memory");
    }

    if (pBlk && qBlk) return;

    if (!pBlk && !qBlk) {
#pragma unroll
        for (int mt = 0; mt < 4; mt++) {
            int m = m0 + wm * 64 + mt * 16 + g;
#pragma unroll
            for (int nt = 0; nt < 8; nt++) {
                int n = n0 + wn * 64 + nt * 8 + 2 * t;
                float v0 = cacc[mt][nt][0]; v0 = (v0 >= 0.f) ? v0 : 0.1f * v0;
                float v1 = cacc[mt][nt][1]; v1 = (v1 >= 0.f) ? v1 : 0.1f * v1;
                float v2 = cacc[mt][nt][2]; v2 = (v2 >= 0.f) ? v2 : 0.1f * v2;
                float v3 = cacc[mt][nt][3]; v3 = (v3 >= 0.f) ? v3 : 0.1f * v3;
                __stcs(S + (size_t)n * MT + m, v0);
                __stcs(S + (size_t)(n + 1) * MT + m, v1);
                __stcs(S + (size_t)n * MT + m + 8, v2);
                __stcs(S + (size_t)(n + 1) * MT + m + 8, v3);
            }
        }
    } else if (pBlk) {
#pragma unroll
        for (int mt = 0; mt < 4; mt++) {
            int m = m0 + wm * 64 + mt * 16 + g;
#pragma unroll
            for (int nt = 0; nt < 8; nt++) {
                int i = wn * 64 + nt * 8 + 2 * t;
                __stcs(g_P + (size_t)i * MT + m, cacc[mt][nt][0]);
                __stcs(g_P + (size_t)(i + 1) * MT + m, cacc[mt][nt][1]);
                __stcs(g_P + (size_t)i * MT + m + 8, cacc[mt][nt][2]);
                __stcs(g_P + (size_t)(i + 1) * MT + m + 8, cacc[mt][nt][3]);
            }
        }
    } else {
#pragma unroll
        for (int mt = 0; mt < 4; mt++) {
            int b = (by - 72) * BM + wm * 64 + mt * 16 + g;
#pragma unroll
            for (int nt = 0; nt < 8; nt++) {
                int n = n0 + wn * 64 + nt * 8 + 2 * t;
                __stcs(g_Q + (size_t)b * NT + n, cacc[mt][nt][0]);
                __stcs(g_Q + (size_t)b * NT + n + 1, cacc[mt][nt][1]);
                __stcs(g_Q + (size_t)(b + 8) * NT + n, cacc[mt][nt][2]);
                __stcs(g_Q + (size_t)(b + 8) * NT + n + 1, cacc[mt][nt][3]);
            }
        }
    }
#undef ISSUE
#undef COMPUTE
}

// ============================ per-pair epilogue: fused w2, 1 pair/block ============================
// word offsets: FS 0 (1600, stride 41) | Am 1600 (40x44) | Cm 3360 (36x44)
//               Hs 4944 (40x40) | Gs 6544 (36x36) | w2p1 7840 (40x9) | w2p2 8200 (36x10)
#define EPI_WORDS 8560
#define EPI_SMEM (EPI_WORDS * 4)

__global__ void __launch_bounds__(128) pair_epilogue(const float* __restrict__ S,
                                                     float* __restrict__ out) {
    extern __shared__ float sh[];
    __shared__ float Pb[NR], Qi[NL], rnl[NR], cnl[NL], s1s[NL], s2s[NR];
    float* FS = sh;
    float* Am = sh + 1600;
    float* Cm = sh + 3360;
    float* Hs = sh + 4944;
    float* Gs = sh + 6544;
    float* w2p1 = sh + 7840;
    float* w2p2 = sh + 8200;
    const int i = blockIdx.x, b = blockIdx.y, tid = threadIdx.x;

    const float* Sp = S + (size_t)i * NL * MT + (size_t)b * NR;
    for (int idx = tid; idx < NR * NL; idx += 128) {
        int l = idx / NR, r = idx - l * NR;
        FS[r * 41 + l] = __ldcs(Sp + (size_t)l * MT + r);
    }
    for (int idx = tid; idx < NR * NR; idx += 128) Gs[idx] = g_G[(size_t)b * (NR * NR) + idx];
    for (int idx = tid; idx < NL * NL; idx += 128) Hs[idx] = g_H[(size_t)i * (NL * NL) + idx];
    if (tid < NR) Pb[tid] = g_P[(size_t)i * MT + b * NR + tid];
    else if (tid >= 64 && tid < 64 + NL) Qi[tid - 64] = g_Q[(size_t)b * NT + i * NL + (tid - 64)];
    __syncthreads();

    if (tid < NL) {                         // column norms over r -> lambda/cn
        int l = tid; float s = 0.f;
#pragma unroll
        for (int r = 0; r < NR; r++) { float v = FS[r * 41 + l]; s = fmaf(v, v, s); }
        cnl[l] = LAMS / (sqrtf(s) + EPSF);
    } else if (tid >= 64 && tid < 64 + NR) { // row norms over l -> lambda/rn
        int r = tid - 64; float s = 0.f;
#pragma unroll
        for (int l = 0; l < NL; l++) { float v = FS[r * 41 + l]; s = fmaf(v, v, s); }
        rnl[r] = LAMS / (sqrtf(s) + EPSF);
    }
    __syncthreads();

    for (int idx = tid; idx < NR * NL; idx += 128) {
        int l = idx / NR, r = idx - l * NR;
        float v = FS[r * 41 + l];
        Am[l * 44 + r] = __expf(v * rnl[r]);
        Cm[r * 44 + l] = __expf(v * cnl[l]);
    }
    __syncthreads();

    // fused mini-GEMM + quadratic form: 180 tasks, each a 4x4 tile
    for (int task = tid; task < 180; task += 128) {
        float4 acc0 = make_float4(0.f, 0.f, 0.f, 0.f);
        float4 acc1 = acc0, acc2 = acc0, acc3 = acc0;
        float4 st0 = acc0, st1 = acc0, st2 = acc0, st3 = acc0;
        if (task < 90) {
            // rows l = 4lg.., cols r = 4rg..; w2p1[l*9+rg] = sum_r tile.a
            int lg = task / 9, rg = task - lg * 9;
            const float* Ab = Am + lg * 4 * 44;
            const float* Gb = Gs + rg * 4;
#pragma unroll
            for (int rp4 = 0; rp4 < 9; rp4++) {
                float4 a0 = *(const float4*)(Ab + rp4 * 4);
                float4 a1 = *(const float4*)(Ab + 44 + rp4 * 4);
                float4 a2 = *(const float4*)(Ab + 88 + rp4 * 4);
                float4 a3 = *(const float4*)(Ab + 132 + rp4 * 4);
                if (rp4 == rg) { st0 = a0; st1 = a1; st2 = a2; st3 = a3; }
                float4 g0 = *(const float4*)(Gb + (rp4 * 4 + 0) * 36);
                float4 g1 = *(const float4*)(Gb + (rp4 * 4 + 1) * 36);
                float4 g2 = *(const float4*)(Gb + (rp4 * 4 + 2) * 36);
                float4 g3 = *(const float4*)(Gb + (rp4 * 4 + 3) * 36);
#define ACC4(ACC, AV)                                                          \
                ACC.x = fmaf(AV.x, g0.x, ACC.x); ACC.y = fmaf(AV.x, g0.y, ACC.y); \
                ACC.z = fmaf(AV.x, g0.z, ACC.z); ACC.w = fmaf(AV.x, g0.w, ACC.w); \
                ACC.x = fmaf(AV.y, g1.x, ACC.x); ACC.y = fmaf(AV.y, g1.y, ACC.y); \
                ACC.z = fmaf(AV.y, g1.z, ACC.z); ACC.w = fmaf(AV.y, g1.w, ACC.w); \
                ACC.x = fmaf(AV.z, g2.x, ACC.x); ACC.y = fmaf(AV.z, g2.y, ACC.y); \
                ACC.z = fmaf(AV.z, g2.z, ACC.z); ACC.w = fmaf(AV.z, g2.w, ACC.w); \
                ACC.x = fmaf(AV.w, g3.x, ACC.x); ACC.y = fmaf(AV.w, g3.y, ACC.y); \
                ACC.z = fmaf(AV.w, g3.z, ACC.z); ACC.w = fmaf(AV.w, g3.w, ACC.w);
                ACC4(acc0, a0) ACC4(acc1, a1) ACC4(acc2, a2) ACC4(acc3, a3)
            }
            int l = lg * 4;
            w2p1[(l + 0) * 9 + rg] = acc0.x * st0.x + acc0.y * st0.y + acc0.z * st0.z + acc0.w * st0.w;
            w2p1[(l + 1) * 9 + rg] = acc1.x * st1.x + acc1.y * st1.y + acc1.z * st1.z + acc1.w * st1.w;
            w2p1[(l + 2) * 9 + rg] = acc2.x * st2.x + acc2.y * st2.y + acc2.z * st2.z + acc2.w * st2.w;
            w2p1[(l + 3) * 9 + rg] = acc3.x * st3.x + acc3.y * st3.y + acc3.z * st3.z + acc3.w * st3.w;
        } else {
            // rows r = 4rg.., cols l = 4lg..; w2p2[r*10+lg]
            int t2 = task - 90;
            int rg = t2 / 10, lg = t2 - rg * 10;
            const float* Cb = Cm + rg * 4 * 44;
            const float* Hb = Hs + lg * 4;
#pragma unroll
            for (int lp4 = 0; lp4 < 10; lp4++) {
                float4 a0 = *(const float4*)(Cb + lp4 * 4);
                float4 a1 = *(const float4*)(Cb + 44 + lp4 * 4);
                float4 a2 = *(const float4*)(Cb + 88 + lp4 * 4);
                float4 a3 = *(const float4*)(Cb + 132 + lp4 * 4);
                if (lp4 == lg) { st0 = a0; st1 = a1; st2 = a2; st3 = a3; }
                float4 g0 = *(const float4*)(Hb + (lp4 * 4 + 0) * 40);
                float4 g1 = *(const float4*)(Hb + (lp4 * 4 + 1) * 40);
                float4 g2 = *(const float4*)(Hb + (lp4 * 4 + 2) * 40);
                float4 g3 = *(const float4*)(Hb + (lp4 * 4 + 3) * 40);
                ACC4(acc0, a0) ACC4(acc1, a1) ACC4(acc2, a2) ACC4(acc3, a3)
#undef ACC4
            }
            int r = rg * 4;
            w2p2[(r + 0) * 10 + lg] = acc0.x * st0.x + acc0.y * st0.y + acc0.z * st0.z + acc0.w * st0.w;
            w2p2[(r + 1) * 10 + lg] = acc1.x * st1.x + acc1.y * st1.y + acc1.z * st1.z + acc1.w * st1.w;
            w2p2[(r + 2) * 10 + lg] = acc2.x * st2.x + acc2.y * st2.y + acc2.z * st2.z + acc2.w * st2.w;
            w2p2[(r + 3) * 10 + lg] = acc3.x * st3.x + acc3.y * st3.y + acc3.z * st3.z + acc3.w * st3.w;
        }
    }
    __syncthreads();

    if (tid < NL) {                          // t2i: word l
        int l = tid; float w12 = 0.f, w2 = 0.f;
#pragma unroll
        for (int r = 0; r < NR; r++) w12 = fmaf(Am[l * 44 + r], Pb[r], w12);
#pragma unroll
        for (int k = 0; k < 9; k++) w2 += w2p1[l * 9 + k];
        float den = fmaxf(g_w1t[i] * sqrtf(fmaxf(w2, 0.f)), EPSF);
        s1s[l] = __fdividef(w12, den);
    } else if (tid >= 64 && tid < 64 + NR) { // i2t: region r
        int r = tid - 64; float w12 = 0.f, w2 = 0.f;
#pragma unroll
        for (int l = 0; l < NL; l++) w12 = fmaf(Cm[r * 44 + l], Qi[l], w12);
#pragma unroll
        for (int k = 0; k < 10; k++) w2 += w2p2[r * 10 + k];
        float den = fmaxf(g_w1i[b] * sqrtf(fmaxf(w2, 0.f)), EPSF);
        s2s[r] = __fdividef(w12, den);
    }
    __syncthreads();

    if (tid == 0) {
        float m1 = 0.f, m2 = 0.f;
#pragma unroll
        for (int l = 0; l < NL; l++) m1 += s1s[l];
#pragma unroll
        for (int r = 0; r < NR; r++) m2 += s2s[r];
        out[(size_t)b * NB + i] = g_base[b * NB + i] + m1 * (1.f / NL) + m2 * (1.f / NR);
    }
}

// ============================ launch ============================
extern "C" void kernel_launch(void* const* d_in, const int* in_sizes, int n_in,
                              void* d_out, int out_size) {
    (void)in_sizes; (void)n_in; (void)out_size;
    const float* pool_img = (const float*)d_in[0];
    const float* img_emb  = (const float*)d_in[1];
    const float* pool_txt = (const float*)d_in[2];
    const float* cap_emb  = (const float*)d_in[3];
    float* out = (float*)d_out;

    cudaFuncSetAttribute((const void*)gram_kernel,
                         cudaFuncAttributeMaxDynamicSharedMemorySize, NL * ND * 4);
    cudaFuncSetAttribute((const void*)s_gemm,
                         cudaFuncAttributeMaxDynamicSharedMemorySize, GEMM_SMEM);
    cudaFuncSetAttribute((const void*)pair_epilogue,
                         cudaFuncAttributeMaxDynamicSharedMemorySize, EPI_SMEM);

    float* dS = nullptr;
    cudaGetSymbolAddress((void**)&dS, g_S);
    __nv_bfloat16* dAh = nullptr; cudaGetSymbolAddress((void**)&dAh, g_Ah);
    __nv_bfloat16* dBh = nullptr; cudaGetSymbolAddress((void**)&dBh, g_Bh);

    // order: s_gemm stays at launch index 3 (profiled slot)
    cvt_kernel<<<9984, 256>>>(img_emb, pool_img, cap_emb, pool_txt);
    gram_kernel<<<NB, 256, NR * ND * 4>>>(img_emb, NR, 0);
    gram_kernel<<<NB, 256, NL * ND * 4>>>(cap_emb, NL, 1);
    s_gemm<<<dim3(41, 74), 256, GEMM_SMEM>>>(dAh, dBh, dS);
    norm_kernel<<<64, 256>>>(pool_img, pool_txt);
    sgemm_tn<<<dim3(NB / 64, NB / 64), 256>>>(pool_img, pool_txt, NB, NB, ND);
    pair_epilogue<<<dim3(NB, NB), 128, EPI_SMEM>>>(dS, out);
}